// round 7
// baseline (speedup 1.0000x reference)
#include <cuda_runtime.h>
#include <cstdint>

#define NN 1024
#define HH 8
#define PADA 132   // 132 % 32 == 4 -> conflict-free frag loads for both A and B^T

// ---------------- scratch (device globals; no allocs) ----------------
__device__ float g_pre1[NN * 128];
__device__ float g_pre2g[NN * 128];
__device__ float g_vals[NN * 128];
__device__ float g_skip[NN * 128];
__device__ float g_gterm[128];
__device__ float g_logits[(size_t)HH * NN * NN];   // [i][h][j] flattened as ((i*8+h)*1024+j)

// ---------------- K0: graph term = graph@Wg + bg + be ----------------
__global__ void k0_gterm(const float* __restrict__ gf, const float* __restrict__ Wg,
                         const float* __restrict__ bg, const float* __restrict__ be) {
    int m = threadIdx.x;
    float a = bg[m] + be[m];
#pragma unroll 8
    for (int k = 0; k < 128; k++) a += gf[k] * Wg[k * 128 + m];
    g_gterm[m] = a;
}

// ---------------- K1: out[j,:] = z[j,:] @ W + bias (+gterm) ----------------
// z = concat(node, hidden) along feature dim (Z=256). Block = 32 rows x 128 cols.
__global__ __launch_bounds__(256) void k1_proj(const float* __restrict__ node,
                                               const float* __restrict__ hid,
                                               const float* __restrict__ W,
                                               const float* __restrict__ bias,
                                               const float* __restrict__ gterm,
                                               float* __restrict__ out) {
    __shared__ float Ws[32 * 132];
    __shared__ float zs[32 * 33];
    int tid = threadIdx.x, lane = tid & 31, warp = tid >> 5;
    int j0 = blockIdx.x * 32;
    float acc[4][4] = {};
    for (int kc = 0; kc < 8; kc++) {
        int kb = kc * 32;
        __syncthreads();
        for (int e = tid; e < 4096; e += 256) {
            int kl = e >> 7, m = e & 127;
            Ws[kl * 132 + m] = W[(kb + kl) * 128 + m];
        }
        for (int e = tid; e < 1024; e += 256) {
            int jl = e >> 5, kl = e & 31;
            int k = kb + kl;
            zs[jl * 33 + kl] = (k < 128) ? node[(j0 + jl) * 128 + k]
                                         : hid[(j0 + jl) * 128 + k - 128];
        }
        __syncthreads();
#pragma unroll 8
        for (int kl = 0; kl < 32; kl++) {
            float4 wv = *(const float4*)&Ws[kl * 132 + lane * 4];
#pragma unroll
            for (int r = 0; r < 4; r++) {
                float zv = zs[(warp * 4 + r) * 33 + kl];
                acc[r][0] += zv * wv.x; acc[r][1] += zv * wv.y;
                acc[r][2] += zv * wv.z; acc[r][3] += zv * wv.w;
            }
        }
    }
    float4 bv = *(const float4*)&bias[lane * 4];
    float4 gv = make_float4(0.f, 0.f, 0.f, 0.f);
    if (gterm) gv = *(const float4*)&gterm[lane * 4];
#pragma unroll
    for (int r = 0; r < 4; r++) {
        float4 o;
        o.x = acc[r][0] + bv.x + gv.x;
        o.y = acc[r][1] + bv.y + gv.y;
        o.z = acc[r][2] + bv.z + gv.z;
        o.w = acc[r][3] + bv.w + gv.w;
        *(float4*)&out[(size_t)(j0 + warp * 4 + r) * 128 + lane * 4] = o;
    }
}

// ---------------- K2 helpers ----------------
__device__ __forceinline__ unsigned f2u(float f) { return __float_as_uint(f); }
__device__ __forceinline__ unsigned cvt_tf32(float f) {
    unsigned r; asm("cvt.rna.tf32.f32 %0, %1;" : "=r"(r) : "f"(f)); return r;
}
__device__ __forceinline__ void cp16(float* dst, const float* src) {
    unsigned s = (unsigned)__cvta_generic_to_shared(dst);
    asm volatile("cp.async.cg.shared.global [%0], [%1], 16;" :: "r"(s), "l"(src));
}
__device__ __forceinline__ void cp_commit() { asm volatile("cp.async.commit_group;"); }
__device__ __forceinline__ void cp_wait1() { asm volatile("cp.async.wait_group 1;"); }
__device__ __forceinline__ void cp_wait0() { asm volatile("cp.async.wait_group 0;"); }

// ---------------- K2: logits GEMM (TF32 mma.sync) + fused epilogue ----------------
// CTA c handles i = c>>1, j-tiles jtb..jtb+3 (jtb = (c&1)*4). 256 threads, warps 4x2 (wm x wn).
// smem: WsT[n][k] (tf32, rna), A double buffer (raw fp32 bits as tf32 => truncation).
__global__ __launch_bounds__(256) void k2_logits(const float* __restrict__ edge,
                                                 const float* __restrict__ We,
                                                 const float* __restrict__ Aw,
                                                 const float* __restrict__ Abv,
                                                 const int* __restrict__ adj) {
    extern __shared__ float sm[];
    float* WsT = sm;
    float* Abuf0 = sm + 128 * PADA;
    float* Abuf1 = sm + 2 * 128 * PADA;
    __shared__ float sAw[128];
    __shared__ float sAb[8];

    int tid = threadIdx.x, lane = tid & 31, warp = tid >> 5;
    int wm = warp >> 1, wn = warp & 1;
    int ro = lane >> 2, kq = lane & 3;
    int cta = blockIdx.x;
    int i = cta >> 1;
    int jtb = (cta & 1) * 4;
    const float* base = edge + (size_t)i * (1024 * 128);

    // prefetch tile 0  (128x128 fp32 tile = 4096 float4s = 16 iters x 256 thr)
    {
        const float* src = base + (size_t)(jtb * 128) * 128;
        for (int it = 0; it < 16; it++) {
            int idx = it * 256 + tid;
            cp16(Abuf0 + (idx >> 5) * PADA + (idx & 31) * 4, src + idx * 4);
        }
        cp_commit();
    }
    // stage We transposed + rna->tf32 (overlaps with cp.async).
    // FULL 128x128 = 16384 elements (was 4096: only k<32 filled -> garbage GEMM).
    for (int e = tid; e < 16384; e += 256) {
        int k = e >> 7, m = e & 127;
        WsT[m * PADA + k] = __uint_as_float(cvt_tf32(We[k * 128 + m]));
    }
    if (tid < 128) sAw[tid] = Aw[tid];
    if (tid < 8)   sAb[tid] = Abv[tid];

    // fixed per-thread columns and dest-node terms
    int colb[8];
    float p2x[8], p2y[8];
#pragma unroll
    for (int ni = 0; ni < 8; ni++) {
        colb[ni] = wn * 64 + ni * 8 + kq * 2;
        float2 v = *(const float2*)&g_pre2g[i * 128 + colb[ni]];
        p2x[ni] = v.x; p2y[ni] = v.y;
    }

    for (int s = 0; s < 4; s++) {
        float* Acur = (s & 1) ? Abuf1 : Abuf0;
        if (s < 3) {
            float* Anxt = (s & 1) ? Abuf0 : Abuf1;
            const float* src = base + (size_t)((jtb + s + 1) * 128) * 128;
            for (int it = 0; it < 16; it++) {
                int idx = it * 256 + tid;
                cp16(Anxt + (idx >> 5) * PADA + (idx & 31) * 4, src + idx * 4);
            }
            cp_commit();
            cp_wait1();
        } else {
            cp_wait0();
        }
        __syncthreads();

        float c[2][8][4];
#pragma unroll
        for (int mi = 0; mi < 2; mi++)
#pragma unroll
            for (int ni = 0; ni < 8; ni++)
#pragma unroll
                for (int r = 0; r < 4; r++) c[mi][ni][r] = 0.f;

#pragma unroll 2
        for (int ks = 0; ks < 16; ks++) {
            int k0 = ks * 8;
            unsigned a[2][4];
#pragma unroll
            for (int mi = 0; mi < 2; mi++) {
                const float* ap = Acur + (wm * 32 + mi * 16 + ro) * PADA + k0 + kq;
                a[mi][0] = f2u(ap[0]);
                a[mi][1] = f2u(ap[8 * PADA]);
                a[mi][2] = f2u(ap[4]);
                a[mi][3] = f2u(ap[8 * PADA + 4]);
            }
            unsigned bf[8][2];
#pragma unroll
            for (int ni = 0; ni < 8; ni++) {
                const float* bp = WsT + (wn * 64 + ni * 8 + ro) * PADA + k0 + kq;
                bf[ni][0] = f2u(bp[0]);
                bf[ni][1] = f2u(bp[4]);
            }
#pragma unroll
            for (int mi = 0; mi < 2; mi++)
#pragma unroll
                for (int ni = 0; ni < 8; ni++)
                    asm volatile(
                        "mma.sync.aligned.m16n8k8.row.col.f32.tf32.tf32.f32 "
                        "{%0,%1,%2,%3}, {%4,%5,%6,%7}, {%8,%9}, {%0,%1,%2,%3};"
                        : "+f"(c[mi][ni][0]), "+f"(c[mi][ni][1]),
                          "+f"(c[mi][ni][2]), "+f"(c[mi][ni][3])
                        : "r"(a[mi][0]), "r"(a[mi][1]), "r"(a[mi][2]), "r"(a[mi][3]),
                          "r"(bf[ni][0]), "r"(bf[ni][1]));
        }

        // epilogue: + pre1[j] + pre2g[i], leaky_relu, per-head dot with A
        int j0 = (jtb + s) * 128;
        float hsum[2][2][4];
#pragma unroll
        for (int mi = 0; mi < 2; mi++)
#pragma unroll
            for (int rr = 0; rr < 2; rr++)
#pragma unroll
                for (int hd = 0; hd < 4; hd++) hsum[mi][rr][hd] = 0.f;

#pragma unroll
        for (int mi = 0; mi < 2; mi++) {
#pragma unroll
            for (int rr = 0; rr < 2; rr++) {
                int row = wm * 32 + mi * 16 + ro + rr * 8;
                const float* p1 = g_pre1 + (size_t)(j0 + row) * 128;
#pragma unroll
                for (int ni = 0; ni < 8; ni++) {
                    float2 pv = *(const float2*)&p1[colb[ni]];
                    float x0 = c[mi][ni][rr * 2 + 0] + pv.x + p2x[ni];
                    float x1 = c[mi][ni][rr * 2 + 1] + pv.y + p2y[ni];
                    x0 = fmaxf(x0, 0.01f * x0);   // leaky_relu, slope 0.01
                    x1 = fmaxf(x1, 0.01f * x1);
                    hsum[mi][rr][ni >> 1] += sAw[colb[ni]] * x0 + sAw[colb[ni] + 1] * x1;
                }
            }
        }
        // reduce across the 4 lanes sharing a row (lane&3 groups)
#pragma unroll
        for (int off = 1; off <= 2; off <<= 1)
#pragma unroll
            for (int mi = 0; mi < 2; mi++)
#pragma unroll
                for (int rr = 0; rr < 2; rr++)
#pragma unroll
                    for (int hd = 0; hd < 4; hd++)
                        hsum[mi][rr][hd] += __shfl_xor_sync(0xffffffffu, hsum[mi][rr][hd], off);

        int q = lane & 3;
        int h = wn * 4 + q;
        float ab = sAb[h];
#pragma unroll
        for (int mi = 0; mi < 2; mi++)
#pragma unroll
            for (int rr = 0; rr < 2; rr++) {
                int row = wm * 32 + mi * 16 + ro + rr * 8;
                int j = j0 + row;
                float lg = hsum[mi][rr][q] + ab + (adj[i * 1024 + j] ? 0.f : -1e9f);
                g_logits[((size_t)i * 8 + h) * 1024 + j] = lg;
            }
        __syncthreads();
    }
}

// ---------------- K3: softmax over j + AV + skip + relu ----------------
// CTA per i; warp per head. logits row (1024) lives in registers; p in smem.
__global__ __launch_bounds__(256) void k3_attn(const float* __restrict__ vals,
                                               const float* __restrict__ skip,
                                               float* __restrict__ out) {
    __shared__ float ps[8][1024];
    int i = blockIdx.x;
    int tid = threadIdx.x, lane = tid & 31, h = tid >> 5;
    const float* lg = g_logits + ((size_t)i * 8 + h) * 1024;

    float4 v[8];
#pragma unroll
    for (int t = 0; t < 8; t++) v[t] = ((const float4*)lg)[t * 32 + lane];

    float mx = -3.402823e38f;
#pragma unroll
    for (int t = 0; t < 8; t++) {
        mx = fmaxf(mx, fmaxf(fmaxf(v[t].x, v[t].y), fmaxf(v[t].z, v[t].w)));
    }
#pragma unroll
    for (int off = 16; off >= 1; off >>= 1)
        mx = fmaxf(mx, __shfl_xor_sync(0xffffffffu, mx, off));

    float ssum = 0.f;
#pragma unroll
    for (int t = 0; t < 8; t++) {
        v[t].x = __expf(v[t].x - mx); v[t].y = __expf(v[t].y - mx);
        v[t].z = __expf(v[t].z - mx); v[t].w = __expf(v[t].w - mx);
        ssum += v[t].x + v[t].y + v[t].z + v[t].w;
        ((float4*)ps[h])[t * 32 + lane] = v[t];
    }
#pragma unroll
    for (int off = 16; off >= 1; off >>= 1)
        ssum += __shfl_xor_sync(0xffffffffu, ssum, off);
    float inv = 1.f / ssum;
    __syncwarp();

    int jg = lane >> 4, hs = lane & 15;
    const float* vp = vals + h * 16 + hs;
    float acc = 0.f;
#pragma unroll 8
    for (int j = jg; j < 1024; j += 2)
        acc += ps[h][j] * vp[(size_t)j * 128];
    acc += __shfl_xor_sync(0xffffffffu, acc, 16);
    if (jg == 0) {
        int o = i * 128 + h * 16 + hs;
        float r = acc * inv + skip[o];
        out[o] = fmaxf(r, 0.f);
    }
}

// ---------------- launch ----------------
extern "C" void kernel_launch(void* const* d_in, const int* in_sizes, int n_in,
                              void* d_out, int out_size) {
    const float* node   = (const float*)d_in[0];
    const float* edge   = (const float*)d_in[1];
    const float* graph  = (const float*)d_in[2];
    const int*   adj    = (const int*)  d_in[3];
    const float* hidden = (const float*)d_in[4];
    const float* Wm     = (const float*)d_in[5];
    const float* bm     = (const float*)d_in[6];
    const float* Wskip  = (const float*)d_in[7];
    const float* bskip  = (const float*)d_in[8];
    const float* W1     = (const float*)d_in[9];
    const float* b1     = (const float*)d_in[10];
    const float* W2     = (const float*)d_in[11];
    const float* b2     = (const float*)d_in[12];
    const float* We     = (const float*)d_in[13];
    const float* be     = (const float*)d_in[14];
    const float* Wg     = (const float*)d_in[15];
    const float* bg     = (const float*)d_in[16];
    const float* Aw     = (const float*)d_in[17];
    const float* Abv    = (const float*)d_in[18];
    float* out = (float*)d_out;

    float *p1, *p2g, *vals, *skip, *gterm;
    cudaGetSymbolAddress((void**)&p1,    g_pre1);
    cudaGetSymbolAddress((void**)&p2g,   g_pre2g);
    cudaGetSymbolAddress((void**)&vals,  g_vals);
    cudaGetSymbolAddress((void**)&skip,  g_skip);
    cudaGetSymbolAddress((void**)&gterm, g_gterm);

    k0_gterm<<<1, 128>>>(graph, Wg, bg, be);
    k1_proj<<<32, 256>>>(node, hidden, Wm,    bm,    nullptr, vals);
    k1_proj<<<32, 256>>>(node, hidden, Wskip, bskip, nullptr, skip);
    k1_proj<<<32, 256>>>(node, hidden, W1,    b1,    nullptr, p1);
    k1_proj<<<32, 256>>>(node, hidden, W2,    b2,    gterm,   p2g);

    const int smem2 = 3 * 128 * PADA * sizeof(float);   // 202752 B
    cudaFuncSetAttribute(k2_logits, cudaFuncAttributeMaxDynamicSharedMemorySize, smem2);
    k2_logits<<<2048, 256, smem2>>>(edge, We, Aw, Abv, adj);

    k3_attn<<<1024, 256>>>(vals, skip, out);
}

// round 8
// speedup vs baseline: 1.2016x; 1.2016x over previous
#include <cuda_runtime.h>
#include <cuda_bf16.h>
#include <cuda_fp16.h>
#include <cstdint>

#define NN 1024
#define HH 8
#define WSTRIDE 72   // 32-bit words per smem row: 64 data + 8 pad; 72%32==8 -> perfect banks for LDS.64 frags

// ---------------- scratch (device globals; no allocs) ----------------
__device__ float g_pre1[NN * 128];
__device__ float g_pre2g[NN * 128];
__device__ float g_vals[NN * 128];
__device__ float g_skip[NN * 128];
__device__ float g_gterm[128];
__device__ float g_logits[(size_t)HH * NN * NN];   // [i][h][j]

// ---------------- K0: graph term = graph@Wg + bg + be ----------------
__global__ void k0_gterm(const float* __restrict__ gf, const float* __restrict__ Wg,
                         const float* __restrict__ bg, const float* __restrict__ be) {
    int m = threadIdx.x;
    float a = bg[m] + be[m];
#pragma unroll 8
    for (int k = 0; k < 128; k++) a += gf[k] * Wg[k * 128 + m];
    g_gterm[m] = a;
}

// ---------------- K1 (fused): all four z-projections in one launch ----------------
// grid (64, 4): blockIdx.x = 16-row tile, blockIdx.y = which W. 256 threads.
__global__ __launch_bounds__(256) void k1_fused(const float* __restrict__ node,
                                                const float* __restrict__ hid,
                                                const float* __restrict__ Wm, const float* __restrict__ bm,
                                                const float* __restrict__ Wsk, const float* __restrict__ bsk,
                                                const float* __restrict__ W1, const float* __restrict__ b1,
                                                const float* __restrict__ W2, const float* __restrict__ b2,
                                                float* __restrict__ vals, float* __restrict__ skip,
                                                float* __restrict__ p1, float* __restrict__ p2g) {
    __shared__ float Ws[32 * 132];
    __shared__ float zs[16 * 33];
    int by = blockIdx.y;
    const float* W    = by == 0 ? Wm : by == 1 ? Wsk : by == 2 ? W1 : W2;
    const float* bias = by == 0 ? bm : by == 1 ? bsk : by == 2 ? b1 : b2;
    float* out        = by == 0 ? vals : by == 1 ? skip : by == 2 ? p1 : p2g;

    int tid = threadIdx.x, lane = tid & 31, warp = tid >> 5;
    int j0 = blockIdx.x * 16;
    float acc[2][4] = {};
    for (int kc = 0; kc < 8; kc++) {
        int kb = kc * 32;
        __syncthreads();
        for (int e = tid; e < 4096; e += 256) {
            int kl = e >> 7, m = e & 127;
            Ws[kl * 132 + m] = W[(kb + kl) * 128 + m];
        }
        for (int e = tid; e < 512; e += 256) {
            int jl = e >> 5, kl = e & 31;
            int k = kb + kl;
            zs[jl * 33 + kl] = (k < 128) ? node[(j0 + jl) * 128 + k]
                                         : hid[(j0 + jl) * 128 + k - 128];
        }
        __syncthreads();
#pragma unroll 8
        for (int kl = 0; kl < 32; kl++) {
            float4 wv = *(const float4*)&Ws[kl * 132 + lane * 4];
#pragma unroll
            for (int r = 0; r < 2; r++) {
                float zv = zs[(warp * 2 + r) * 33 + kl];
                acc[r][0] += zv * wv.x; acc[r][1] += zv * wv.y;
                acc[r][2] += zv * wv.z; acc[r][3] += zv * wv.w;
            }
        }
    }
    float4 bv = *(const float4*)&bias[lane * 4];
    float4 gv = make_float4(0.f, 0.f, 0.f, 0.f);
    if (by == 3) gv = *(const float4*)&g_gterm[lane * 4];
#pragma unroll
    for (int r = 0; r < 2; r++) {
        float4 o;
        o.x = acc[r][0] + bv.x + gv.x;
        o.y = acc[r][1] + bv.y + gv.y;
        o.z = acc[r][2] + bv.z + gv.z;
        o.w = acc[r][3] + bv.w + gv.w;
        *(float4*)&out[(size_t)(j0 + warp * 2 + r) * 128 + lane * 4] = o;
    }
}

// ---------------- K2 helpers ----------------
__device__ __forceinline__ unsigned bfbits(__nv_bfloat162 h) { return *(unsigned*)&h; }
// k-pair slot permutation inside each 16-k chunk: pairs (kq, kq+4) land adjacent
__device__ __forceinline__ int kslot(int p) {
    return ((p & 3) << 1) | ((p >> 2) & 1) | ((p >> 3) << 3);
}

// ---------------- K2: logits GEMM (bf16 m16n8k16) + fused epilogue ----------------
// CTA c: i = c>>1, j-tiles jtb..jtb+3. 256 threads, warps 4x2 (wm x wn), warp tile 32m x 64n.
// smem: A double buffer (bf16, k-permuted), Bs = We^T bf16. 110.6 KB -> 2 CTAs/SM.
__global__ __launch_bounds__(256, 2) void k2_logits(const float* __restrict__ edge,
                                                    const float* __restrict__ We,
                                                    const float* __restrict__ Aw,
                                                    const float* __restrict__ Abv,
                                                    const int* __restrict__ adj) {
    extern __shared__ unsigned smw[];
    unsigned* As0 = smw;
    unsigned* As1 = smw + 128 * WSTRIDE;
    unsigned* Bs  = smw + 2 * 128 * WSTRIDE;
    __shared__ float sAw[128];
    __shared__ float sAb[8];

    int tid = threadIdx.x, lane = tid & 31, warp = tid >> 5;
    int wm = warp >> 1, wn = warp & 1;
    int ro = lane >> 2, kq = lane & 3;
    int cta = blockIdx.x;
    int i = cta >> 1;
    int jtb = (cta & 1) * 4;
    const float* base = edge + (size_t)i * (1024 * 128);

    // stage Bs = We^T as bf16 (one-time)
    for (int e = tid; e < 8192; e += 256) {
        int m = e & 127, p = e >> 7;
        float f0 = We[(2 * p) * 128 + m];
        float f1 = We[(2 * p + 1) * 128 + m];
        Bs[m * WSTRIDE + kslot(p)] = bfbits(__floats2bfloat162_rn(f0, f1));
    }
    // stage tile 0 -> As0
    {
        const float* src = base + (size_t)(jtb * 128) * 128;
        for (int it = 0; it < 16; it++) {
            int idx = it * 256 + tid;
            int row = idx >> 5, q = idx & 31;
            float4 f = *(const float4*)(src + idx * 4);
            As0[row * WSTRIDE + kslot(2 * q)]     = bfbits(__floats2bfloat162_rn(f.x, f.y));
            As0[row * WSTRIDE + kslot(2 * q + 1)] = bfbits(__floats2bfloat162_rn(f.z, f.w));
        }
    }
    if (tid < 128) sAw[tid] = Aw[tid];
    if (tid < 8)   sAb[tid] = Abv[tid];

    int colb[8];
    float p2x[8], p2y[8];
#pragma unroll
    for (int ni = 0; ni < 8; ni++) {
        colb[ni] = wn * 64 + ni * 8 + kq * 2;
        float2 v = *(const float2*)&g_pre2g[i * 128 + colb[ni]];
        p2x[ni] = v.x; p2y[ni] = v.y;
    }
    __syncthreads();

    for (int s = 0; s < 4; s++) {
        unsigned* Acur = (s & 1) ? As1 : As0;
        unsigned* Anxt = (s & 1) ? As0 : As1;
        const float* srcn = base + (size_t)((jtb + s + 1) * 128) * 128;
        bool doldg = (s < 3);

        float c[2][8][4];
#pragma unroll
        for (int mi = 0; mi < 2; mi++)
#pragma unroll
            for (int ni = 0; ni < 8; ni++)
#pragma unroll
                for (int r = 0; r < 4; r++) c[mi][ni][r] = 0.f;

        // 4 segments: each prefetches 1/4 of next tile, computes 2 k16-steps, stores prefetch
#pragma unroll
        for (int seg = 0; seg < 4; seg++) {
            float4 pre[4];
            if (doldg) {
#pragma unroll
                for (int t = 0; t < 4; t++) {
                    int idx = (seg * 4 + t) * 256 + tid;
                    pre[t] = __ldg((const float4*)(srcn + idx * 4));
                }
            }
#pragma unroll
            for (int kk = 0; kk < 2; kk++) {
                int ks = seg * 2 + kk;
                int fo = ks * 8 + 2 * kq;
                unsigned a[2][4];
#pragma unroll
                for (int mi = 0; mi < 2; mi++) {
                    int rb = (wm * 32 + mi * 16 + ro) * WSTRIDE + fo;
                    uint2 t0 = *(const uint2*)&Acur[rb];
                    uint2 t1 = *(const uint2*)&Acur[rb + 8 * WSTRIDE];
                    a[mi][0] = t0.x; a[mi][1] = t1.x; a[mi][2] = t0.y; a[mi][3] = t1.y;
                }
                uint2 b[8];
#pragma unroll
                for (int ni = 0; ni < 8; ni++)
                    b[ni] = *(const uint2*)&Bs[(wn * 64 + ni * 8 + ro) * WSTRIDE + fo];
#pragma unroll
                for (int mi = 0; mi < 2; mi++)
#pragma unroll
                    for (int ni = 0; ni < 8; ni++)
                        asm volatile(
                            "mma.sync.aligned.m16n8k16.row.col.f32.bf16.bf16.f32 "
                            "{%0,%1,%2,%3}, {%4,%5,%6,%7}, {%8,%9}, {%0,%1,%2,%3};"
                            : "+f"(c[mi][ni][0]), "+f"(c[mi][ni][1]),
                              "+f"(c[mi][ni][2]), "+f"(c[mi][ni][3])
                            : "r"(a[mi][0]), "r"(a[mi][1]), "r"(a[mi][2]), "r"(a[mi][3]),
                              "r"(b[ni].x), "r"(b[ni].y));
            }
            if (doldg) {
#pragma unroll
                for (int t = 0; t < 4; t++) {
                    int idx = (seg * 4 + t) * 256 + tid;
                    int row = idx >> 5, q = idx & 31;
                    Anxt[row * WSTRIDE + kslot(2 * q)]     = bfbits(__floats2bfloat162_rn(pre[t].x, pre[t].y));
                    Anxt[row * WSTRIDE + kslot(2 * q + 1)] = bfbits(__floats2bfloat162_rn(pre[t].z, pre[t].w));
                }
            }
        }

        // epilogue: + pre1[j] + pre2g[i], leaky_relu, per-head dot with A
        int j0 = (jtb + s) * 128;
        float hsum[2][2][4];
#pragma unroll
        for (int mi = 0; mi < 2; mi++)
#pragma unroll
            for (int rr = 0; rr < 2; rr++)
#pragma unroll
                for (int hd = 0; hd < 4; hd++) hsum[mi][rr][hd] = 0.f;

#pragma unroll
        for (int mi = 0; mi < 2; mi++) {
#pragma unroll
            for (int rr = 0; rr < 2; rr++) {
                int row = wm * 32 + mi * 16 + ro + rr * 8;
                const float* p1 = g_pre1 + (size_t)(j0 + row) * 128;
#pragma unroll
                for (int ni = 0; ni < 8; ni++) {
                    float2 pv = *(const float2*)&p1[colb[ni]];
                    float x0 = c[mi][ni][rr * 2 + 0] + pv.x + p2x[ni];
                    float x1 = c[mi][ni][rr * 2 + 1] + pv.y + p2y[ni];
                    x0 = fmaxf(x0, 0.01f * x0);
                    x1 = fmaxf(x1, 0.01f * x1);
                    hsum[mi][rr][ni >> 1] += sAw[colb[ni]] * x0 + sAw[colb[ni] + 1] * x1;
                }
            }
        }
#pragma unroll
        for (int off = 1; off <= 2; off <<= 1)
#pragma unroll
            for (int mi = 0; mi < 2; mi++)
#pragma unroll
                for (int rr = 0; rr < 2; rr++)
#pragma unroll
                    for (int hd = 0; hd < 4; hd++)
                        hsum[mi][rr][hd] += __shfl_xor_sync(0xffffffffu, hsum[mi][rr][hd], off);

        int q = lane & 3;
        int h = wn * 4 + q;
        float ab = sAb[h];
#pragma unroll
        for (int mi = 0; mi < 2; mi++)
#pragma unroll
            for (int rr = 0; rr < 2; rr++) {
                int row = wm * 32 + mi * 16 + ro + rr * 8;
                int j = j0 + row;
                float lg = hsum[mi][rr][q] + ab + (adj[i * 1024 + j] ? 0.f : -1e9f);
                g_logits[((size_t)i * 8 + h) * 1024 + j] = lg;
            }
        __syncthreads();
    }
}

// ---------------- K3: softmax + AV + skip + relu, 4 i's per CTA ----------------
// grid 256; warp = head. Phase 1: softmax probs -> fp16 smem. Phase 2: stream vals once for 4 i's.
__global__ __launch_bounds__(256) void k3_attn(const float* __restrict__ vals,
                                               const float* __restrict__ skip,
                                               float* __restrict__ out) {
    extern __shared__ __half ps[];   // [4][8][1024]
    int i0 = blockIdx.x * 4;
    int tid = threadIdx.x, lane = tid & 31, h = tid >> 5;

    float inv4[4];
#pragma unroll
    for (int ii = 0; ii < 4; ii++) {
        const float* lg = g_logits + ((size_t)(i0 + ii) * 8 + h) * 1024;
        float4 v[8];
#pragma unroll
        for (int t = 0; t < 8; t++) v[t] = ((const float4*)lg)[t * 32 + lane];
        float mx = -3.402823e38f;
#pragma unroll
        for (int t = 0; t < 8; t++)
            mx = fmaxf(mx, fmaxf(fmaxf(v[t].x, v[t].y), fmaxf(v[t].z, v[t].w)));
#pragma unroll
        for (int off = 16; off >= 1; off >>= 1)
            mx = fmaxf(mx, __shfl_xor_sync(0xffffffffu, mx, off));
        float ssum = 0.f;
        __half* pr = ps + ((ii * 8 + h) << 10);
#pragma unroll
        for (int t = 0; t < 8; t++) {
            v[t].x = __expf(v[t].x - mx); v[t].y = __expf(v[t].y - mx);
            v[t].z = __expf(v[t].z - mx); v[t].w = __expf(v[t].w - mx);
            ssum += v[t].x + v[t].y + v[t].z + v[t].w;
            __half2 ha = __floats2half2_rn(v[t].x, v[t].y);
            __half2 hb = __floats2half2_rn(v[t].z, v[t].w);
            *(uint2*)&pr[(t * 32 + lane) * 4] = make_uint2(*(unsigned*)&ha, *(unsigned*)&hb);
        }
#pragma unroll
        for (int off = 16; off >= 1; off >>= 1)
            ssum += __shfl_xor_sync(0xffffffffu, ssum, off);
        inv4[ii] = 1.f / ssum;
    }
    __syncthreads();

    int jg = lane >> 4, hs = lane & 15;
    const float* vp = vals + h * 16 + hs;
    float acc[4] = {0.f, 0.f, 0.f, 0.f};
#pragma unroll 8
    for (int j = jg; j < 1024; j += 2) {
        float vv = __ldg(&vp[(size_t)j * 128]);
#pragma unroll
        for (int ii = 0; ii < 4; ii++)
            acc[ii] += __half2float(ps[((ii * 8 + h) << 10) + j]) * vv;
    }
#pragma unroll
    for (int ii = 0; ii < 4; ii++)
        acc[ii] += __shfl_xor_sync(0xffffffffu, acc[ii], 16);
    if (jg == 0) {
#pragma unroll
        for (int ii = 0; ii < 4; ii++) {
            int o = (i0 + ii) * 128 + h * 16 + hs;
            out[o] = fmaxf(acc[ii] * inv4[ii] + skip[o], 0.f);
        }
    }
}

// ---------------- launch ----------------
extern "C" void kernel_launch(void* const* d_in, const int* in_sizes, int n_in,
                              void* d_out, int out_size) {
    const float* node   = (const float*)d_in[0];
    const float* edge   = (const float*)d_in[1];
    const float* graph  = (const float*)d_in[2];
    const int*   adj    = (const int*)  d_in[3];
    const float* hidden = (const float*)d_in[4];
    const float* Wm     = (const float*)d_in[5];
    const float* bm     = (const float*)d_in[6];
    const float* Wskip  = (const float*)d_in[7];
    const float* bskip  = (const float*)d_in[8];
    const float* W1     = (const float*)d_in[9];
    const float* b1     = (const float*)d_in[10];
    const float* W2     = (const float*)d_in[11];
    const float* b2     = (const float*)d_in[12];
    const float* We     = (const float*)d_in[13];
    const float* be     = (const float*)d_in[14];
    const float* Wg     = (const float*)d_in[15];
    const float* bg     = (const float*)d_in[16];
    const float* Aw     = (const float*)d_in[17];
    const float* Abv    = (const float*)d_in[18];
    float* out = (float*)d_out;

    float *p1, *p2g, *vals, *skip;
    cudaGetSymbolAddress((void**)&p1,   g_pre1);
    cudaGetSymbolAddress((void**)&p2g,  g_pre2g);
    cudaGetSymbolAddress((void**)&vals, g_vals);
    cudaGetSymbolAddress((void**)&skip, g_skip);

    k0_gterm<<<1, 128>>>(graph, Wg, bg, be);
    k1_fused<<<dim3(64, 4), 256>>>(node, hidden, Wm, bm, Wskip, bskip,
                                   W1, b1, W2, b2, vals, skip, p1, p2g);

    const int smem2 = 3 * 128 * WSTRIDE * sizeof(unsigned);   // 110592 B
    cudaFuncSetAttribute(k2_logits, cudaFuncAttributeMaxDynamicSharedMemorySize, smem2);
    k2_logits<<<2048, 256, smem2>>>(edge, We, Aw, Abv, adj);

    const int smem3 = 4 * 8 * 1024 * sizeof(__half);          // 65536 B
    cudaFuncSetAttribute(k3_attn, cudaFuncAttributeMaxDynamicSharedMemorySize, smem3);
    k3_attn<<<256, 256, smem3>>>(vals, skip, out);
}

// round 10
// speedup vs baseline: 1.2544x; 1.0439x over previous
#include <cuda_runtime.h>
#include <cuda_fp16.h>
#include <cstdint>

#define NN 1024
#define ASTRIDE 36                 // words per A-chunk row (32 data + 4 pad): banks 4*ro+kq -> conflict-free
#define ACHUNK (256 * ASTRIDE)     // 9216 words per 256x32 chunk
#define BSTRIDE 132                // words per B row (128 data + 4 pad)

// ---------------- scratch (device globals; no allocs) ----------------
__device__ float g_pre1[NN * 128];        // [j][m]
__device__ float g_pre2g[NN * 128];
__device__ float g_valsT[128 * NN];       // TRANSPOSED: [m][j]
__device__ float g_skip[NN * 128];
__device__ float g_gterm[128];
__device__ float g_logits[(size_t)8 * NN * NN];   // [i][h][j]

// ---------------- helpers ----------------
__device__ __forceinline__ unsigned f2u(float f) { return __float_as_uint(f); }
__device__ __forceinline__ void cp16f(float* dst, const float* src) {
    unsigned s = (unsigned)__cvta_generic_to_shared(dst);
    asm volatile("cp.async.cg.shared.global [%0], [%1], 16;" :: "r"(s), "l"(src));
}
__device__ __forceinline__ void cp_commit() { asm volatile("cp.async.commit_group;"); }
__device__ __forceinline__ void cp_wait0() { asm volatile("cp.async.wait_group 0;"); }
__device__ __forceinline__ void cp_wait1() { asm volatile("cp.async.wait_group 1;"); }
__device__ __forceinline__ void cp_wait2() { asm volatile("cp.async.wait_group 2;"); }

// ---------------- K0 ----------------
__global__ void k0_gterm(const float* __restrict__ gf, const float* __restrict__ Wg,
                         const float* __restrict__ bg, const float* __restrict__ be) {
    int m = threadIdx.x;
    float a = bg[m] + be[m];
#pragma unroll 8
    for (int k = 0; k < 128; k++) a += gf[k] * Wg[k * 128 + m];
    g_gterm[m] = a;
}

// ---------------- K1 (fused 4 projections); vals written transposed ----------------
__global__ __launch_bounds__(256) void k1_fused(const float* __restrict__ node,
                                                const float* __restrict__ hid,
                                                const float* __restrict__ Wm, const float* __restrict__ bm,
                                                const float* __restrict__ Wsk, const float* __restrict__ bsk,
                                                const float* __restrict__ W1, const float* __restrict__ b1,
                                                const float* __restrict__ W2, const float* __restrict__ b2) {
    __shared__ float Ws[32 * 132];
    __shared__ float zs[16 * 33];
    int by = blockIdx.y;
    const float* W    = by == 0 ? Wm : by == 1 ? Wsk : by == 2 ? W1 : W2;
    const float* bias = by == 0 ? bm : by == 1 ? bsk : by == 2 ? b1 : b2;

    int tid = threadIdx.x, lane = tid & 31, warp = tid >> 5;
    int j0 = blockIdx.x * 16;
    float acc[2][4] = {};
    for (int kc = 0; kc < 8; kc++) {
        int kb = kc * 32;
        __syncthreads();
        for (int e = tid; e < 4096; e += 256) {
            int kl = e >> 7, m = e & 127;
            Ws[kl * 132 + m] = W[(kb + kl) * 128 + m];
        }
        for (int e = tid; e < 512; e += 256) {
            int jl = e >> 5, kl = e & 31;
            int k = kb + kl;
            zs[jl * 33 + kl] = (k < 128) ? node[(j0 + jl) * 128 + k]
                                         : hid[(j0 + jl) * 128 + k - 128];
        }
        __syncthreads();
#pragma unroll 8
        for (int kl = 0; kl < 32; kl++) {
            float4 wv = *(const float4*)&Ws[kl * 132 + lane * 4];
#pragma unroll
            for (int r = 0; r < 2; r++) {
                float zv = zs[(warp * 2 + r) * 33 + kl];
                acc[r][0] += zv * wv.x; acc[r][1] += zv * wv.y;
                acc[r][2] += zv * wv.z; acc[r][3] += zv * wv.w;
            }
        }
    }
    float4 bv = *(const float4*)&bias[lane * 4];
    float4 gv = make_float4(0.f, 0.f, 0.f, 0.f);
    if (by == 3) gv = *(const float4*)&g_gterm[lane * 4];
#pragma unroll
    for (int r = 0; r < 2; r++) {
        int j = j0 + warp * 2 + r;
        float o[4];
        o[0] = acc[r][0] + bv.x + gv.x;
        o[1] = acc[r][1] + bv.y + gv.y;
        o[2] = acc[r][2] + bv.z + gv.z;
        o[3] = acc[r][3] + bv.w + gv.w;
        if (by == 0) {
#pragma unroll
            for (int c = 0; c < 4; c++)
                g_valsT[(size_t)(lane * 4 + c) * NN + j] = o[c];
        } else {
            float* out = by == 1 ? g_skip : by == 2 ? g_pre1 : g_pre2g;
            *(float4*)&out[(size_t)j * 128 + lane * 4] = make_float4(o[0], o[1], o[2], o[3]);
        }
    }
}

// ---------------- K2: tf32 mma.sync, 64x64 warp tiles, k-chunk cp.async ring ----------------
// CTA c: i = c>>1, j range [ (c&1)*512, +512 ) as 2 super-tiles of 256 rows.
// 8 warps = 4(wm) x 2(wn), warp tile 64m x 64n. A ring: 3 chunks of 256x32 fp32.
__global__ __launch_bounds__(256, 1) void k2_logits(const float* __restrict__ edge,
                                                    const float* __restrict__ We,
                                                    const float* __restrict__ Aw,
                                                    const float* __restrict__ Abv,
                                                    const int* __restrict__ adj) {
    extern __shared__ float sm[];
    float* Bs = sm;                       // 128*132 = 16896 words
    float* As = sm + 16896;               // 3 * 9216 words
    __shared__ float sAw[128], sP2[128], sAb[8];

    int tid = threadIdx.x, lane = tid & 31, warp = tid >> 5;
    int wm = warp >> 1, wn = warp & 1;
    int ro = lane >> 2, kq = lane & 3;
    int i = blockIdx.x >> 1, jh = blockIdx.x & 1;
    const float* base = edge + (size_t)i * 131072 + (size_t)jh * 512 * 128;

    // stage B = We^T fp32 (tf32 via HW truncation)
    for (int e = tid; e < 16384; e += 256) {
        int k = e >> 7, m = e & 127;
        Bs[m * BSTRIDE + k] = We[k * 128 + m];
    }
    if (tid < 128) { sAw[tid] = Aw[tid]; sP2[tid] = g_pre2g[i * 128 + tid]; }
    if (tid < 8)   sAb[tid] = Abv[tid];

    // prefetch chunks 0..2 (chunk gc: super-tile gc>>2, k-block gc&3)
    for (int gc = 0; gc < 3; gc++) {
        const float* src = base + (size_t)((gc >> 2) * 256) * 128 + (gc & 3) * 32;
        float* dst = As + gc * ACHUNK;
#pragma unroll
        for (int it = 0; it < 8; it++) {
            int idx = it * 256 + tid;
            int row = idx >> 3, q = idx & 7;
            cp16f(dst + row * ASTRIDE + q * 4, src + (size_t)row * 128 + q * 4);
        }
        cp_commit();
    }

    float c[4][8][4];
#pragma unroll
    for (int mi = 0; mi < 4; mi++)
#pragma unroll
        for (int ni = 0; ni < 8; ni++)
#pragma unroll
            for (int r = 0; r < 4; r++) c[mi][ni][r] = 0.f;

    int buf = 0;
    for (int gc = 0; gc < 8; gc++) {
        if (gc >= 6) { if (gc == 7) cp_wait0(); else cp_wait1(); }
        else cp_wait2();
        __syncthreads();

        const float* Ab = As + buf * ACHUNK;
#pragma unroll
        for (int ks = 0; ks < 4; ks++) {
            int kf = ks * 8 + kq;
            unsigned a[4][4];
#pragma unroll
            for (int mi = 0; mi < 4; mi++) {
                const float* ap = Ab + (wm * 64 + mi * 16 + ro) * ASTRIDE + kf;
                a[mi][0] = f2u(ap[0]);
                a[mi][1] = f2u(ap[8 * ASTRIDE]);
                a[mi][2] = f2u(ap[4]);
                a[mi][3] = f2u(ap[8 * ASTRIDE + 4]);
            }
            int kg = (gc & 3) * 32 + kf;
            unsigned b[8][2];
#pragma unroll
            for (int ni = 0; ni < 8; ni++) {
                const float* bp = Bs + (wn * 64 + ni * 8 + ro) * BSTRIDE + kg;
                b[ni][0] = f2u(bp[0]);
                b[ni][1] = f2u(bp[4]);
            }
#pragma unroll
            for (int mi = 0; mi < 4; mi++)
#pragma unroll
                for (int ni = 0; ni < 8; ni++)
                    asm volatile(
                        "mma.sync.aligned.m16n8k8.row.col.f32.tf32.tf32.f32 "
                        "{%0,%1,%2,%3}, {%4,%5,%6,%7}, {%8,%9}, {%0,%1,%2,%3};"
                        : "+f"(c[mi][ni][0]), "+f"(c[mi][ni][1]),
                          "+f"(c[mi][ni][2]), "+f"(c[mi][ni][3])
                        : "r"(a[mi][0]), "r"(a[mi][1]), "r"(a[mi][2]), "r"(a[mi][3]),
                          "r"(b[ni][0]), "r"(b[ni][1]));
        }
        __syncthreads();

        if (gc < 5) {   // prefetch chunk gc+3 into the buffer just freed
            int nc = gc + 3;
            const float* src = base + (size_t)((nc >> 2) * 256) * 128 + (nc & 3) * 32;
            float* dst = As + buf * ACHUNK;
#pragma unroll
            for (int it = 0; it < 8; it++) {
                int idx = it * 256 + tid;
                int row = idx >> 3, q = idx & 7;
                cp16f(dst + row * ASTRIDE + q * 4, src + (size_t)row * 128 + q * 4);
            }
            cp_commit();
        }

        if ((gc & 3) == 3) {
            // epilogue for super-tile st = gc>>2
            int st = gc >> 2;
            int j0 = jh * 512 + st * 256;
            float hs4[4][2][4];
#pragma unroll
            for (int mi = 0; mi < 4; mi++)
#pragma unroll
                for (int rr = 0; rr < 2; rr++)
#pragma unroll
                    for (int hd = 0; hd < 4; hd++) hs4[mi][rr][hd] = 0.f;

#pragma unroll
            for (int mi = 0; mi < 4; mi++) {
#pragma unroll
                for (int rr = 0; rr < 2; rr++) {
                    int jrow = j0 + wm * 64 + mi * 16 + ro + rr * 8;
                    const float* p1 = g_pre1 + (size_t)jrow * 128;
#pragma unroll
                    for (int ni = 0; ni < 8; ni++) {
                        int cb = wn * 64 + ni * 8 + kq * 2;
                        float2 pv = *(const float2*)&p1[cb];
                        float x0 = c[mi][ni][rr * 2 + 0] + pv.x + sP2[cb];
                        float x1 = c[mi][ni][rr * 2 + 1] + pv.y + sP2[cb + 1];
                        x0 = fmaxf(x0, 0.01f * x0);
                        x1 = fmaxf(x1, 0.01f * x1);
                        hs4[mi][rr][ni >> 1] += sAw[cb] * x0 + sAw[cb + 1] * x1;
                    }
                }
            }
#pragma unroll
            for (int off = 1; off <= 2; off <<= 1)
#pragma unroll
                for (int mi = 0; mi < 4; mi++)
#pragma unroll
                    for (int rr = 0; rr < 2; rr++)
#pragma unroll
                        for (int hd = 0; hd < 4; hd++)
                            hs4[mi][rr][hd] += __shfl_xor_sync(0xffffffffu, hs4[mi][rr][hd], off);

            int q = lane & 3;
            int h = wn * 4 + q;
            float ab = sAb[h];
#pragma unroll
            for (int mi = 0; mi < 4; mi++)
#pragma unroll
                for (int rr = 0; rr < 2; rr++) {
                    int j = j0 + wm * 64 + mi * 16 + ro + rr * 8;
                    float lg = hs4[mi][rr][q] + ab + (adj[i * 1024 + j] ? 0.f : -1e9f);
                    g_logits[((size_t)i * 8 + h) * 1024 + j] = lg;
                }
            // reset accumulators for next super-tile
#pragma unroll
            for (int mi = 0; mi < 4; mi++)
#pragma unroll
                for (int ni = 0; ni < 8; ni++)
#pragma unroll
                    for (int r = 0; r < 4; r++) c[mi][ni][r] = 0.f;
        }
        buf = (buf == 2) ? 0 : buf + 1;
    }
}

// ---------------- K3: softmax + AV + skip + relu; 2 i's per CTA, valsT streaming ----------------
__global__ __launch_bounds__(256) void k3_attn(const float* __restrict__ skip,
                                               float* __restrict__ out) {
    extern __shared__ __half ps[];   // [2][8][1024]
    int i0 = blockIdx.x * 2;
    int tid = threadIdx.x, lane = tid & 31, h = tid >> 5;

    float inv2[2];
#pragma unroll
    for (int ii = 0; ii < 2; ii++) {
        const float* lg = g_logits + ((size_t)(i0 + ii) * 8 + h) * 1024;
        float4 v[8];
#pragma unroll
        for (int t = 0; t < 8; t++) v[t] = ((const float4*)lg)[t * 32 + lane];
        float mx = -3.402823e38f;
#pragma unroll
        for (int t = 0; t < 8; t++)
            mx = fmaxf(mx, fmaxf(fmaxf(v[t].x, v[t].y), fmaxf(v[t].z, v[t].w)));
#pragma unroll
        for (int off = 16; off >= 1; off >>= 1)
            mx = fmaxf(mx, __shfl_xor_sync(0xffffffffu, mx, off));
        float ssum = 0.f;
        __half* pr = ps + ((ii * 8 + h) << 10);
#pragma unroll
        for (int t = 0; t < 8; t++) {
            v[t].x = __expf(v[t].x - mx); v[t].y = __expf(v[t].y - mx);
            v[t].z = __expf(v[t].z - mx); v[t].w = __expf(v[t].w - mx);
            ssum += v[t].x + v[t].y + v[t].z + v[t].w;
            __half2 ha = __floats2half2_rn(v[t].x, v[t].y);
            __half2 hb = __floats2half2_rn(v[t].z, v[t].w);
            *(uint2*)&pr[(t * 32 + lane) * 4] = make_uint2(*(unsigned*)&ha, *(unsigned*)&hb);
        }
#pragma unroll
        for (int off = 16; off >= 1; off >>= 1)
            ssum += __shfl_xor_sync(0xffffffffu, ssum, off);
        inv2[ii] = 1.f / ssum;
    }
    __syncthreads();

    // AV: lane -> (jhalf, hs); valsT row streaming with float4
    int jhalf = lane >> 4, hs = lane & 15;
    const float4* vrow = (const float4*)(g_valsT + (size_t)(h * 16 + hs) * NN + jhalf * 512);
    const __half2* pp = (const __half2*)ps;
    float acc[2] = {0.f, 0.f};
#pragma unroll 4
    for (int t = 0; t < 128; t++) {
        float4 vv = vrow[t];
        int jb2 = (jhalf * 512 + t * 4) >> 1;
#pragma unroll
        for (int ii = 0; ii < 2; ii++) {
            float2 fa = __half22float2(pp[((ii * 8 + h) << 9) + jb2]);
            float2 fb = __half22float2(pp[((ii * 8 + h) << 9) + jb2 + 1]);
            acc[ii] += fa.x * vv.x + fa.y * vv.y + fb.x * vv.z + fb.y * vv.w;
        }
    }
#pragma unroll
    for (int ii = 0; ii < 2; ii++)
        acc[ii] += __shfl_xor_sync(0xffffffffu, acc[ii], 16);
    if (jhalf == 0) {
#pragma unroll
        for (int ii = 0; ii < 2; ii++) {
            int o = (i0 + ii) * 128 + h * 16 + hs;
            out[o] = fmaxf(acc[ii] * inv2[ii] + skip[o], 0.f);
        }
    }
}

// ---------------- launch ----------------
extern "C" void kernel_launch(void* const* d_in, const int* in_sizes, int n_in,
                              void* d_out, int out_size) {
    const float* node   = (const float*)d_in[0];
    const float* edge   = (const float*)d_in[1];
    const float* graph  = (const float*)d_in[2];
    const int*   adj    = (const int*)  d_in[3];
    const float* hidden = (const float*)d_in[4];
    const float* Wm     = (const float*)d_in[5];
    const float* bm     = (const float*)d_in[6];
    const float* Wskip  = (const float*)d_in[7];
    const float* bskip  = (const float*)d_in[8];
    const float* W1     = (const float*)d_in[9];
    const float* b1     = (const float*)d_in[10];
    const float* W2     = (const float*)d_in[11];
    const float* b2     = (const float*)d_in[12];
    const float* We     = (const float*)d_in[13];
    const float* be     = (const float*)d_in[14];
    const float* Wg     = (const float*)d_in[15];
    const float* bg     = (const float*)d_in[16];
    const float* Aw     = (const float*)d_in[17];
    const float* Abv    = (const float*)d_in[18];
    float* out = (float*)d_out;

    float* skip;
    cudaGetSymbolAddress((void**)&skip, g_skip);

    k0_gterm<<<1, 128>>>(graph, Wg, bg, be);
    k1_fused<<<dim3(64, 4), 256>>>(node, hidden, Wm, bm, Wskip, bskip, W1, b1, W2, b2);

    const int smem2 = (16896 + 3 * ACHUNK) * sizeof(float);   // 178,176 B
    cudaFuncSetAttribute(k2_logits, cudaFuncAttributeMaxDynamicSharedMemorySize, smem2);
    k2_logits<<<2048, 256, smem2>>>(edge, We, Aw, Abv, adj);

    const int smem3 = 2 * 8 * 1024 * sizeof(__half);          // 32,768 B
    cudaFuncSetAttribute(k3_attn, cudaFuncAttributeMaxDynamicSharedMemorySize, smem3);
    k3_attn<<<512, 256, smem3>>>(skip, out);
}

// round 11
// speedup vs baseline: 1.5940x; 1.2707x over previous
#include <cuda_runtime.h>
#include <cuda_fp16.h>
#include <cstdint>

#define NN 1024
#define ASTRIDE 40                 // words/row of A chunk (32 data + 8 pad): LDS.64 frags conflict-free
#define ACHUNK (256 * ASTRIDE)     // 10240 words per 256x32 chunk
#define BSH 136                    // halfs per B row (128 data + 8 pad): LDS.32 frags conflict-free

// ---------------- scratch (device globals; no allocs) ----------------
__device__ float g_pre1[NN * 128];        // [j][m]
__device__ float g_pre2g[NN * 128];
__device__ float g_vals[NN * 128];        // [j][c]
__device__ float g_skip[NN * 128];
__device__ float g_gterm[128];
__device__ float g_logits[(size_t)8 * NN * NN];   // [i][h][j]
__device__ __half g_probs[(size_t)8 * NN * NN];   // normalized softmax probs, fp16

// ---------------- helpers ----------------
__device__ __forceinline__ unsigned h2u(__half2 h) { return *(unsigned*)&h; }
__device__ __forceinline__ void cp16f(float* dst, const float* src) {
    unsigned s = (unsigned)__cvta_generic_to_shared(dst);
    asm volatile("cp.async.cg.shared.global [%0], [%1], 16;" :: "r"(s), "l"(src));
}
__device__ __forceinline__ void cp_commit() { asm volatile("cp.async.commit_group;"); }
__device__ __forceinline__ void cp_wait0() { asm volatile("cp.async.wait_group 0;"); }
__device__ __forceinline__ void cp_wait1() { asm volatile("cp.async.wait_group 1;"); }
__device__ __forceinline__ void cp_wait2() { asm volatile("cp.async.wait_group 2;"); }

// ---------------- K0 ----------------
__global__ void k0_gterm(const float* __restrict__ gf, const float* __restrict__ Wg,
                         const float* __restrict__ bg, const float* __restrict__ be) {
    int m = threadIdx.x;
    float a = bg[m] + be[m];
#pragma unroll 8
    for (int k = 0; k < 128; k++) a += gf[k] * Wg[k * 128 + m];
    g_gterm[m] = a;
}

// ---------------- K1 (fused 4 projections) ----------------
__global__ __launch_bounds__(256) void k1_fused(const float* __restrict__ node,
                                                const float* __restrict__ hid,
                                                const float* __restrict__ Wm, const float* __restrict__ bm,
                                                const float* __restrict__ Wsk, const float* __restrict__ bsk,
                                                const float* __restrict__ W1, const float* __restrict__ b1,
                                                const float* __restrict__ W2, const float* __restrict__ b2) {
    __shared__ float Ws[32 * 132];
    __shared__ float zs[16 * 33];
    int by = blockIdx.y;
    const float* W    = by == 0 ? Wm : by == 1 ? Wsk : by == 2 ? W1 : W2;
    const float* bias = by == 0 ? bm : by == 1 ? bsk : by == 2 ? b1 : b2;

    int tid = threadIdx.x, lane = tid & 31, warp = tid >> 5;
    int j0 = blockIdx.x * 16;
    float acc[2][4] = {};
    for (int kc = 0; kc < 8; kc++) {
        int kb = kc * 32;
        __syncthreads();
        for (int e = tid; e < 4096; e += 256) {
            int kl = e >> 7, m = e & 127;
            Ws[kl * 132 + m] = W[(kb + kl) * 128 + m];
        }
        for (int e = tid; e < 512; e += 256) {
            int jl = e >> 5, kl = e & 31;
            int k = kb + kl;
            zs[jl * 33 + kl] = (k < 128) ? node[(j0 + jl) * 128 + k]
                                         : hid[(j0 + jl) * 128 + k - 128];
        }
        __syncthreads();
#pragma unroll 8
        for (int kl = 0; kl < 32; kl++) {
            float4 wv = *(const float4*)&Ws[kl * 132 + lane * 4];
#pragma unroll
            for (int r = 0; r < 2; r++) {
                float zv = zs[(warp * 2 + r) * 33 + kl];
                acc[r][0] += zv * wv.x; acc[r][1] += zv * wv.y;
                acc[r][2] += zv * wv.z; acc[r][3] += zv * wv.w;
            }
        }
    }
    float4 bv = *(const float4*)&bias[lane * 4];
    float4 gv = make_float4(0.f, 0.f, 0.f, 0.f);
    if (by == 3) gv = *(const float4*)&g_gterm[lane * 4];
    float* out = by == 0 ? g_vals : by == 1 ? g_skip : by == 2 ? g_pre1 : g_pre2g;
#pragma unroll
    for (int r = 0; r < 2; r++) {
        int j = j0 + warp * 2 + r;
        float4 o;
        o.x = acc[r][0] + bv.x + gv.x;
        o.y = acc[r][1] + bv.y + gv.y;
        o.z = acc[r][2] + bv.z + gv.z;
        o.w = acc[r][3] + bv.w + gv.w;
        *(float4*)&out[(size_t)j * 128 + lane * 4] = o;
    }
}

// ---------------- K2: fp16 m16n8k16 mma, 64x64 warp tiles, k-chunk cp.async ring ----------------
// CTA c: i = c>>1, j range [(c&1)*512, +512) as 2 super-tiles of 256 rows.
// 8 warps = 4(wm) x 2(wn), warp tile 64m x 64n. A ring: 3 chunks of 256x32 fp32 (cvt to fp16 at frag load).
__global__ __launch_bounds__(256, 1) void k2_logits(const float* __restrict__ edge,
                                                    const float* __restrict__ We,
                                                    const float* __restrict__ Aw,
                                                    const float* __restrict__ Abv,
                                                    const int* __restrict__ adj) {
    extern __shared__ float sm[];
    float* As = sm;                               // 3 * 10240 words
    __half* Bsh = (__half*)(sm + 3 * ACHUNK);     // 128 * 136 halfs
    __shared__ float sAw[128], sP2[128], sAb[8];

    int tid = threadIdx.x, lane = tid & 31, warp = tid >> 5;
    int wm = warp >> 1, wn = warp & 1;
    int ro = lane >> 2, kq = lane & 3;
    int i = blockIdx.x >> 1, jh = blockIdx.x & 1;
    const float* base = edge + (size_t)i * 131072 + (size_t)jh * 512 * 128;

    // stage B = We^T as fp16
    for (int e = tid; e < 16384; e += 256) {
        int k = e >> 7, m = e & 127;
        Bsh[m * BSH + k] = __float2half_rn(We[k * 128 + m]);
    }
    if (tid < 128) { sAw[tid] = Aw[tid]; sP2[tid] = g_pre2g[i * 128 + tid]; }
    if (tid < 8)   sAb[tid] = Abv[tid];

    // prefetch chunks 0..2 (chunk gc: super-tile gc>>2, k-block gc&3)
    for (int gc = 0; gc < 3; gc++) {
        const float* src = base + (size_t)((gc >> 2) * 256) * 128 + (gc & 3) * 32;
        float* dst = As + gc * ACHUNK;
#pragma unroll
        for (int it = 0; it < 8; it++) {
            int idx = it * 256 + tid;
            int row = idx >> 3, q = idx & 7;
            cp16f(dst + row * ASTRIDE + q * 4, src + (size_t)row * 128 + q * 4);
        }
        cp_commit();
    }

    float c[4][8][4];
#pragma unroll
    for (int mi = 0; mi < 4; mi++)
#pragma unroll
        for (int ni = 0; ni < 8; ni++)
#pragma unroll
            for (int r = 0; r < 4; r++) c[mi][ni][r] = 0.f;

    int buf = 0;
    for (int gc = 0; gc < 8; gc++) {
        if (gc >= 6) { if (gc == 7) cp_wait0(); else cp_wait1(); }
        else cp_wait2();
        __syncthreads();

        const float* Ab = As + buf * ACHUNK;
#pragma unroll
        for (int ks = 0; ks < 2; ks++) {          // 2 x k16 per 32-k chunk
            int kf = ks * 16 + 2 * kq;
            unsigned a[4][4];
#pragma unroll
            for (int mi = 0; mi < 4; mi++) {
                const float* ap = Ab + (wm * 64 + mi * 16 + ro) * ASTRIDE + kf;
                float2 f0 = *(const float2*)ap;                      // (ro,   k..k+1)
                float2 f1 = *(const float2*)(ap + 8 * ASTRIDE);      // (ro+8, k..k+1)
                float2 f2 = *(const float2*)(ap + 8);                // (ro,   k+8..k+9)
                float2 f3 = *(const float2*)(ap + 8 * ASTRIDE + 8);  // (ro+8, k+8..k+9)
                a[mi][0] = h2u(__floats2half2_rn(f0.x, f0.y));
                a[mi][1] = h2u(__floats2half2_rn(f1.x, f1.y));
                a[mi][2] = h2u(__floats2half2_rn(f2.x, f2.y));
                a[mi][3] = h2u(__floats2half2_rn(f3.x, f3.y));
            }
            int kg = (gc & 3) * 32 + kf;
            unsigned b[8][2];
#pragma unroll
            for (int ni = 0; ni < 8; ni++) {
                const __half* bp = Bsh + (wn * 64 + ni * 8 + ro) * BSH + kg;
                b[ni][0] = *(const unsigned*)bp;           // (k..k+1,  col ro)
                b[ni][1] = *(const unsigned*)(bp + 8);     // (k+8..k+9, col ro)
            }
#pragma unroll
            for (int mi = 0; mi < 4; mi++)
#pragma unroll
                for (int ni = 0; ni < 8; ni++)
                    asm volatile(
                        "mma.sync.aligned.m16n8k16.row.col.f32.f16.f16.f32 "
                        "{%0,%1,%2,%3}, {%4,%5,%6,%7}, {%8,%9}, {%0,%1,%2,%3};"
                        : "+f"(c[mi][ni][0]), "+f"(c[mi][ni][1]),
                          "+f"(c[mi][ni][2]), "+f"(c[mi][ni][3])
                        : "r"(a[mi][0]), "r"(a[mi][1]), "r"(a[mi][2]), "r"(a[mi][3]),
                          "r"(b[ni][0]), "r"(b[ni][1]));
        }
        __syncthreads();

        if (gc < 5) {   // prefetch chunk gc+3 into the buffer just freed
            int nc = gc + 3;
            const float* src = base + (size_t)((nc >> 2) * 256) * 128 + (nc & 3) * 32;
            float* dst = As + buf * ACHUNK;
#pragma unroll
            for (int it = 0; it < 8; it++) {
                int idx = it * 256 + tid;
                int row = idx >> 3, q = idx & 7;
                cp16f(dst + row * ASTRIDE + q * 4, src + (size_t)row * 128 + q * 4);
            }
            cp_commit();
        }

        if ((gc & 3) == 3) {
            // epilogue for super-tile st = gc>>2
            int st = gc >> 2;
            int j0 = jh * 512 + st * 256;
            float hs4[4][2][4];
#pragma unroll
            for (int mi = 0; mi < 4; mi++)
#pragma unroll
                for (int rr = 0; rr < 2; rr++)
#pragma unroll
                    for (int hd = 0; hd < 4; hd++) hs4[mi][rr][hd] = 0.f;

#pragma unroll
            for (int mi = 0; mi < 4; mi++) {
#pragma unroll
                for (int rr = 0; rr < 2; rr++) {
                    int jrow = j0 + wm * 64 + mi * 16 + ro + rr * 8;
                    const float* p1 = g_pre1 + (size_t)jrow * 128;
#pragma unroll
                    for (int ni = 0; ni < 8; ni++) {
                        int cb = wn * 64 + ni * 8 + kq * 2;
                        float2 pv = *(const float2*)&p1[cb];
                        float x0 = c[mi][ni][rr * 2 + 0] + pv.x + sP2[cb];
                        float x1 = c[mi][ni][rr * 2 + 1] + pv.y + sP2[cb + 1];
                        x0 = fmaxf(x0, 0.01f * x0);
                        x1 = fmaxf(x1, 0.01f * x1);
                        hs4[mi][rr][ni >> 1] += sAw[cb] * x0 + sAw[cb + 1] * x1;
                    }
                }
            }
#pragma unroll
            for (int off = 1; off <= 2; off <<= 1)
#pragma unroll
                for (int mi = 0; mi < 4; mi++)
#pragma unroll
                    for (int rr = 0; rr < 2; rr++)
#pragma unroll
                        for (int hd = 0; hd < 4; hd++)
                            hs4[mi][rr][hd] += __shfl_xor_sync(0xffffffffu, hs4[mi][rr][hd], off);

            int q = lane & 3;
            int h = wn * 4 + q;
            float ab = sAb[h];
#pragma unroll
            for (int mi = 0; mi < 4; mi++)
#pragma unroll
                for (int rr = 0; rr < 2; rr++) {
                    int j = j0 + wm * 64 + mi * 16 + ro + rr * 8;
                    float lg = hs4[mi][rr][q] + ab + (adj[i * 1024 + j] ? 0.f : -1e9f);
                    g_logits[((size_t)i * 8 + h) * 1024 + j] = lg;
                }
#pragma unroll
            for (int mi = 0; mi < 4; mi++)
#pragma unroll
                for (int ni = 0; ni < 8; ni++)
#pragma unroll
                    for (int r = 0; r < 4; r++) c[mi][ni][r] = 0.f;
        }
        buf = (buf == 2) ? 0 : buf + 1;
    }
}

// ---------------- K3a: softmax -> normalized fp16 probs ----------------
// CTA per i, warp per head.
__global__ __launch_bounds__(256) void k3a_softmax() {
    int i = blockIdx.x;
    int tid = threadIdx.x, lane = tid & 31, h = tid >> 5;
    const float* lg = g_logits + ((size_t)(i * 8 + h)) * 1024;

    float4 v[8];
#pragma unroll
    for (int t = 0; t < 8; t++) v[t] = ((const float4*)lg)[t * 32 + lane];
    float mx = -3.402823e38f;
#pragma unroll
    for (int t = 0; t < 8; t++)
        mx = fmaxf(mx, fmaxf(fmaxf(v[t].x, v[t].y), fmaxf(v[t].z, v[t].w)));
#pragma unroll
    for (int off = 16; off >= 1; off >>= 1)
        mx = fmaxf(mx, __shfl_xor_sync(0xffffffffu, mx, off));
    float ssum = 0.f;
#pragma unroll
    for (int t = 0; t < 8; t++) {
        v[t].x = __expf(v[t].x - mx); v[t].y = __expf(v[t].y - mx);
        v[t].z = __expf(v[t].z - mx); v[t].w = __expf(v[t].w - mx);
        ssum += v[t].x + v[t].y + v[t].z + v[t].w;
    }
#pragma unroll
    for (int off = 16; off >= 1; off >>= 1)
        ssum += __shfl_xor_sync(0xffffffffu, ssum, off);
    float inv = 1.f / ssum;

    __half* pr = g_probs + ((size_t)(i * 8 + h)) * 1024;
#pragma unroll
    for (int t = 0; t < 8; t++) {
        __half2 ha = __floats2half2_rn(v[t].x * inv, v[t].y * inv);
        __half2 hb = __floats2half2_rn(v[t].z * inv, v[t].w * inv);
        *(uint2*)&pr[(t * 32 + lane) * 4] = make_uint2(h2u(ha), h2u(hb));
    }
}

// ---------------- K3b: AV + skip + relu ----------------
// grid (32, 8): CTA = 32 i-rows x head h. Vs[1024][16] stride 17; Ps fp16 tiles 32x128 stride 132.
__global__ __launch_bounds__(256) void k3b_av(float* __restrict__ out) {
    extern __shared__ float s3[];
    float* Vs = s3;                                  // 1024*17 floats = 69632 B
    __half* Ps = (__half*)(s3 + 1024 * 17);          // 32*132 halfs = 8448 B
    uint2* Psu = (uint2*)Ps;

    int i0 = blockIdx.x * 32, h = blockIdx.y;
    int tid = threadIdx.x;
    int il = tid >> 3, c0 = tid & 7;

    // stage V_h: Vs[j][c] = g_vals[j*128 + h*16 + c]
    for (int e = tid; e < 16384; e += 256) {
        int j = e >> 4, cc = e & 15;
        Vs[j * 17 + cc] = g_vals[(size_t)j * 128 + h * 16 + cc];
    }

    float acc0 = 0.f, acc1 = 0.f;
    for (int jt = 0; jt < 8; jt++) {
        __syncthreads();
        // stage Ps[32][128] fp16 (uint2 view: row stride 33)
        for (int e = tid; e < 1024; e += 256) {
            int r = e >> 5, q = e & 31;
            const __half* src = g_probs + ((size_t)(i0 + r) * 8 + h) * 1024 + jt * 128;
            Psu[r * 33 + q] = *(const uint2*)(src + q * 4);
        }
        __syncthreads();
        const __half2* prow = (const __half2*)(Ps + il * 132);
        const float* vbase = Vs + (jt * 128) * 17;
#pragma unroll 8
        for (int jj2 = 0; jj2 < 64; jj2++) {
            float2 pf = __half22float2(prow[jj2]);
            const float* v0 = vbase + (2 * jj2) * 17;
            acc0 += pf.x * v0[c0]      + pf.y * v0[17 + c0];
            acc1 += pf.x * v0[c0 + 8]  + pf.y * v0[17 + c0 + 8];
        }
    }
    int o = (i0 + il) * 128 + h * 16 + c0;
    out[o]     = fmaxf(acc0 + g_skip[o], 0.f);
    out[o + 8] = fmaxf(acc1 + g_skip[o + 8], 0.f);
}

// ---------------- launch ----------------
extern "C" void kernel_launch(void* const* d_in, const int* in_sizes, int n_in,
                              void* d_out, int out_size) {
    const float* node   = (const float*)d_in[0];
    const float* edge   = (const float*)d_in[1];
    const float* graph  = (const float*)d_in[2];
    const int*   adj    = (const int*)  d_in[3];
    const float* hidden = (const float*)d_in[4];
    const float* Wm     = (const float*)d_in[5];
    const float* bm     = (const float*)d_in[6];
    const float* Wskip  = (const float*)d_in[7];
    const float* bskip  = (const float*)d_in[8];
    const float* W1     = (const float*)d_in[9];
    const float* b1     = (const float*)d_in[10];
    const float* W2     = (const float*)d_in[11];
    const float* b2     = (const float*)d_in[12];
    const float* We     = (const float*)d_in[13];
    const float* be     = (const float*)d_in[14];
    const float* Wg     = (const float*)d_in[15];
    const float* bg     = (const float*)d_in[16];
    const float* Aw     = (const float*)d_in[17];
    const float* Abv    = (const float*)d_in[18];
    float* out = (float*)d_out;

    k0_gterm<<<1, 128>>>(graph, Wg, bg, be);
    k1_fused<<<dim3(64, 4), 256>>>(node, hidden, Wm, bm, Wskip, bskip, W1, b1, W2, b2);

    const int smem2 = 3 * ACHUNK * sizeof(float) + 128 * BSH * sizeof(__half);  // 157,696 B
    cudaFuncSetAttribute(k2_logits, cudaFuncAttributeMaxDynamicSharedMemorySize, smem2);
    k2_logits<<<2048, 256, smem2>>>(edge, We, Aw, Abv, adj);

    k3a_softmax<<<1024, 256>>>();

    const int smem3 = 1024 * 17 * sizeof(float) + 32 * 132 * sizeof(__half);    // 78,080 B
    cudaFuncSetAttribute(k3b_av, cudaFuncAttributeMaxDynamicSharedMemorySize, smem3);
    k3b_av<<<dim3(32, 8), 256, smem3>>>(out);
}

// round 12
// speedup vs baseline: 1.8212x; 1.1426x over previous
#include <cuda_runtime.h>
#include <cuda_fp16.h>
#include <cstdint>

#define NN 1024

// ---------------- scratch (device globals; no allocs) ----------------
__device__ float g_pre1[NN * 128];        // [j][m]
__device__ float g_pre2g[NN * 128];
__device__ float g_vals[NN * 128];        // [j][c]
__device__ float g_skip[NN * 128];
__device__ float g_gterm[128];
__device__ float g_logits[(size_t)8 * NN * NN];   // [i][h][j]
__device__ __half g_probs[(size_t)8 * NN * NN];   // normalized softmax probs, fp16

// ---------------- helpers ----------------
__device__ __forceinline__ unsigned h2u(__half2 h) { return *(unsigned*)&h; }

// ---------------- K0 ----------------
__global__ void k0_gterm(const float* __restrict__ gf, const float* __restrict__ Wg,
                         const float* __restrict__ bg, const float* __restrict__ be) {
    int m = threadIdx.x;
    float a = bg[m] + be[m];
#pragma unroll 8
    for (int k = 0; k < 128; k++) a += gf[k] * Wg[k * 128 + m];
    g_gterm[m] = a;
}

// ---------------- K1 (fused 4 projections) ----------------
__global__ __launch_bounds__(256) void k1_fused(const float* __restrict__ node,
                                                const float* __restrict__ hid,
                                                const float* __restrict__ Wm, const float* __restrict__ bm,
                                                const float* __restrict__ Wsk, const float* __restrict__ bsk,
                                                const float* __restrict__ W1, const float* __restrict__ b1,
                                                const float* __restrict__ W2, const float* __restrict__ b2) {
    __shared__ float Ws[32 * 132];
    __shared__ float zs[16 * 33];
    int by = blockIdx.y;
    const float* W    = by == 0 ? Wm : by == 1 ? Wsk : by == 2 ? W1 : W2;
    const float* bias = by == 0 ? bm : by == 1 ? bsk : by == 2 ? b1 : b2;

    int tid = threadIdx.x, lane = tid & 31, warp = tid >> 5;
    int j0 = blockIdx.x * 16;
    float acc[2][4] = {};
    for (int kc = 0; kc < 8; kc++) {
        int kb = kc * 32;
        __syncthreads();
        for (int e = tid; e < 4096; e += 256) {
            int kl = e >> 7, m = e & 127;
            Ws[kl * 132 + m] = W[(kb + kl) * 128 + m];
        }
        for (int e = tid; e < 512; e += 256) {
            int jl = e >> 5, kl = e & 31;
            int k = kb + kl;
            zs[jl * 33 + kl] = (k < 128) ? node[(j0 + jl) * 128 + k]
                                         : hid[(j0 + jl) * 128 + k - 128];
        }
        __syncthreads();
#pragma unroll 8
        for (int kl = 0; kl < 32; kl++) {
            float4 wv = *(const float4*)&Ws[kl * 132 + lane * 4];
#pragma unroll
            for (int r = 0; r < 2; r++) {
                float zv = zs[(warp * 2 + r) * 33 + kl];
                acc[r][0] += zv * wv.x; acc[r][1] += zv * wv.y;
                acc[r][2] += zv * wv.z; acc[r][3] += zv * wv.w;
            }
        }
    }
    float4 bv = *(const float4*)&bias[lane * 4];
    float4 gv = make_float4(0.f, 0.f, 0.f, 0.f);
    if (by == 3) gv = *(const float4*)&g_gterm[lane * 4];
    float* out = by == 0 ? g_vals : by == 1 ? g_skip : by == 2 ? g_pre1 : g_pre2g;
#pragma unroll
    for (int r = 0; r < 2; r++) {
        int j = j0 + warp * 2 + r;
        float4 o;
        o.x = acc[r][0] + bv.x + gv.x;
        o.y = acc[r][1] + bv.y + gv.y;
        o.z = acc[r][2] + bv.z + gv.z;
        o.w = acc[r][3] + bv.w + gv.w;
        *(float4*)&out[(size_t)j * 128 + lane * 4] = o;
    }
}

// ---------------- K2: persistent fp16 m16n8k16, 2 CTAs/SM, fp16 A in smem ----------------
// Grid 296 (2/SM). Item = (i, jt): 128x128x128 GEMM tile + fused epilogue. 8192 items.
// 8 warps = 2(wm) x 4(wn), warp tile 64m x 32n. A: 2 buffers of 128x32 fp16 (stride 40 halfs).
// B = We^T fp16 (stride 136 halfs), staged ONCE per CTA. A staged via LDG.128->cvt->STS.64.
__global__ __launch_bounds__(256, 2) void k2_logits(const float* __restrict__ edge,
                                                    const float* __restrict__ We,
                                                    const float* __restrict__ Aw,
                                                    const float* __restrict__ Abv,
                                                    const int* __restrict__ adj) {
    extern __shared__ __half sh[];
    __half* Abuf[2] = { sh, sh + 5120 };          // 2 x 128*40 halfs
    __half* Bsh = sh + 10240;                     // 128*136 halfs
    __shared__ float sAw[128], sAb[8];

    int tid = threadIdx.x, lane = tid & 31, warp = tid >> 5;
    int wm = warp >> 2, wn = warp & 3;
    int ro = lane >> 2, kq = lane & 3;

    int p = blockIdx.x;                            // 0..295
    int npi = 27 + (p < 200);
    int start = p * 27 + (p < 200 ? p : 200);
    int nchunks = npi * 4;

    // stage B = We^T fp16 once
    for (int e = tid; e < 16384; e += 256) {
        int k = e >> 7, m = e & 127;
        Bsh[m * 136 + k] = __float2half_rn(We[k * 128 + m]);
    }
    if (tid < 128) sAw[tid] = Aw[tid];
    if (tid < 8)   sAb[tid] = Abv[tid];

    // chunk source pointer: cidx -> (item, kc)
    auto chunk_src = [&](int cidx) -> const float* {
        int item = start + (cidx >> 2);
        int i = item >> 3, jt = item & 7, kc = cidx & 3;
        return edge + (size_t)i * 131072 + (size_t)(jt * 128) * 128 + kc * 32;
    };

    // prologue: stage chunk 0 into Abuf[0]
    {
        const float* src = chunk_src(0);
        float4 r[4];
#pragma unroll
        for (int it = 0; it < 4; it++) {
            int idx = it * 256 + tid;
            r[it] = __ldg((const float4*)(src + (idx >> 3) * 128 + (idx & 7) * 4));
        }
#pragma unroll
        for (int it = 0; it < 4; it++) {
            int idx = it * 256 + tid;
            int row = idx >> 3, q = idx & 7;
            __half2 h0 = __floats2half2_rn(r[it].x, r[it].y);
            __half2 h1 = __floats2half2_rn(r[it].z, r[it].w);
            *(uint2*)(Abuf[0] + row * 40 + q * 4) = make_uint2(h2u(h0), h2u(h1));
        }
    }
    __syncthreads();

    float c[4][4][4];
#pragma unroll
    for (int mi = 0; mi < 4; mi++)
#pragma unroll
        for (int ni = 0; ni < 4; ni++)
#pragma unroll
            for (int r = 0; r < 4; r++) c[mi][ni][r] = 0.f;

    int cur = 0;
    for (int cidx = 0; cidx < nchunks; cidx++) {
        bool more = (cidx + 1 < nchunks);
        // stage next chunk into registers (hidden behind MMA phase)
        float4 rg[4];
        if (more) {
            const float* src = chunk_src(cidx + 1);
#pragma unroll
            for (int it = 0; it < 4; it++) {
                int idx = it * 256 + tid;
                rg[it] = __ldg((const float4*)(src + (idx >> 3) * 128 + (idx & 7) * 4));
            }
        }

        // MMA phase over current buffer
        const __half* Ab = Abuf[cur];
        int kc = cidx & 3;
#pragma unroll
        for (int ks = 0; ks < 2; ks++) {
            int kf = ks * 16 + 2 * kq;
            int kg = kc * 32 + kf;
            unsigned b[4][2];
#pragma unroll
            for (int ni = 0; ni < 4; ni++) {
                const __half* bp = Bsh + (wn * 32 + ni * 8 + ro) * 136 + kg;
                b[ni][0] = *(const unsigned*)bp;
                b[ni][1] = *(const unsigned*)(bp + 8);
            }
#pragma unroll
            for (int mi = 0; mi < 4; mi++) {
                int r0 = (wm * 64 + mi * 16 + ro) * 40 + kf;
                unsigned a0 = *(const unsigned*)(Ab + r0);
                unsigned a1 = *(const unsigned*)(Ab + r0 + 320);
                unsigned a2 = *(const unsigned*)(Ab + r0 + 8);
                unsigned a3 = *(const unsigned*)(Ab + r0 + 328);
#pragma unroll
                for (int ni = 0; ni < 4; ni++)
                    asm volatile(
                        "mma.sync.aligned.m16n8k16.row.col.f32.f16.f16.f32 "
                        "{%0,%1,%2,%3}, {%4,%5,%6,%7}, {%8,%9}, {%0,%1,%2,%3};"
                        : "+f"(c[mi][ni][0]), "+f"(c[mi][ni][1]),
                          "+f"(c[mi][ni][2]), "+f"(c[mi][ni][3])
                        : "r"(a0), "r"(a1), "r"(a2), "r"(a3),
                          "r"(b[ni][0]), "r"(b[ni][1]));
            }
        }

        if (kc == 3) {
            // epilogue for finished item
            int item = start + (cidx >> 2);
            int i = item >> 3, j0 = (item & 7) * 128;

            float p2x[4], p2y[4];
#pragma unroll
            for (int ni = 0; ni < 4; ni++) {
                int cb = wn * 32 + ni * 8 + kq * 2;
                float2 pv = __ldg((const float2*)&g_pre2g[i * 128 + cb]);
                p2x[ni] = pv.x; p2y[ni] = pv.y;
            }
            float hsum[4][2][2];
#pragma unroll
            for (int mi = 0; mi < 4; mi++)
#pragma unroll
                for (int rr = 0; rr < 2; rr++) {
                    hsum[mi][rr][0] = 0.f; hsum[mi][rr][1] = 0.f;
                }
#pragma unroll
            for (int mi = 0; mi < 4; mi++) {
#pragma unroll
                for (int rr = 0; rr < 2; rr++) {
                    int jrow = j0 + wm * 64 + mi * 16 + ro + rr * 8;
                    const float* p1 = g_pre1 + (size_t)jrow * 128;
#pragma unroll
                    for (int ni = 0; ni < 4; ni++) {
                        int cb = wn * 32 + ni * 8 + kq * 2;
                        float2 pv = __ldg((const float2*)&p1[cb]);
                        float x0 = c[mi][ni][rr * 2 + 0] + pv.x + p2x[ni];
                        float x1 = c[mi][ni][rr * 2 + 1] + pv.y + p2y[ni];
                        x0 = fmaxf(x0, 0.01f * x0);
                        x1 = fmaxf(x1, 0.01f * x1);
                        hsum[mi][rr][ni >> 1] += sAw[cb] * x0 + sAw[cb + 1] * x1;
                    }
                }
            }
#pragma unroll
            for (int off = 1; off <= 2; off <<= 1)
#pragma unroll
                for (int mi = 0; mi < 4; mi++)
#pragma unroll
                    for (int rr = 0; rr < 2; rr++) {
                        hsum[mi][rr][0] += __shfl_xor_sync(0xffffffffu, hsum[mi][rr][0], off);
                        hsum[mi][rr][1] += __shfl_xor_sync(0xffffffffu, hsum[mi][rr][1], off);
                    }
            int q = lane & 3;
            if (q < 2) {
                int h = wn * 2 + q;
                float ab = sAb[h];
#pragma unroll
                for (int mi = 0; mi < 4; mi++)
#pragma unroll
                    for (int rr = 0; rr < 2; rr++) {
                        int j = j0 + wm * 64 + mi * 16 + ro + rr * 8;
                        float lg = hsum[mi][rr][q] + ab
                                 + (__ldg(&adj[i * 1024 + j]) ? 0.f : -1e9f);
                        g_logits[((size_t)i * 8 + h) * 1024 + j] = lg;
                    }
            }
            // reset accumulators
#pragma unroll
            for (int mi = 0; mi < 4; mi++)
#pragma unroll
                for (int ni = 0; ni < 4; ni++)
#pragma unroll
                    for (int r = 0; r < 4; r++) c[mi][ni][r] = 0.f;
        }

        __syncthreads();   // all reads of the other buffer (chunk cidx-1) complete
        if (more) {
            __half* dst = Abuf[cur ^ 1];
#pragma unroll
            for (int it = 0; it < 4; it++) {
                int idx = it * 256 + tid;
                int row = idx >> 3, q = idx & 7;
                __half2 h0 = __floats2half2_rn(rg[it].x, rg[it].y);
                __half2 h1 = __floats2half2_rn(rg[it].z, rg[it].w);
                *(uint2*)(dst + row * 40 + q * 4) = make_uint2(h2u(h0), h2u(h1));
            }
        }
        __syncthreads();   // STS visible before next chunk's MMAs
        cur ^= 1;
    }
}

// ---------------- K3a: softmax -> normalized fp16 probs ----------------
__global__ __launch_bounds__(256) void k3a_softmax() {
    int i = blockIdx.x;
    int tid = threadIdx.x, lane = tid & 31, h = tid >> 5;
    const float* lg = g_logits + ((size_t)(i * 8 + h)) * 1024;

    float4 v[8];
#pragma unroll
    for (int t = 0; t < 8; t++) v[t] = ((const float4*)lg)[t * 32 + lane];
    float mx = -3.402823e38f;
#pragma unroll
    for (int t = 0; t < 8; t++)
        mx = fmaxf(mx, fmaxf(fmaxf(v[t].x, v[t].y), fmaxf(v[t].z, v[t].w)));
#pragma unroll
    for (int off = 16; off >= 1; off >>= 1)
        mx = fmaxf(mx, __shfl_xor_sync(0xffffffffu, mx, off));
    float ssum = 0.f;
#pragma unroll
    for (int t = 0; t < 8; t++) {
        v[t].x = __expf(v[t].x - mx); v[t].y = __expf(v[t].y - mx);
        v[t].z = __expf(v[t].z - mx); v[t].w = __expf(v[t].w - mx);
        ssum += v[t].x + v[t].y + v[t].z + v[t].w;
    }
#pragma unroll
    for (int off = 16; off >= 1; off >>= 1)
        ssum += __shfl_xor_sync(0xffffffffu, ssum, off);
    float inv = 1.f / ssum;

    __half* pr = g_probs + ((size_t)(i * 8 + h)) * 1024;
#pragma unroll
    for (int t = 0; t < 8; t++) {
        __half2 ha = __floats2half2_rn(v[t].x * inv, v[t].y * inv);
        __half2 hb = __floats2half2_rn(v[t].z * inv, v[t].w * inv);
        *(uint2*)&pr[(t * 32 + lane) * 4] = make_uint2(h2u(ha), h2u(hb));
    }
}

// ---------------- K3b: AV + skip + relu ----------------
__global__ __launch_bounds__(256) void k3b_av(float* __restrict__ out) {
    extern __shared__ float s3[];
    float* Vs = s3;                                  // 1024*17 floats
    __half* Ps = (__half*)(s3 + 1024 * 17);          // 32*132 halfs
    uint2* Psu = (uint2*)Ps;

    int i0 = blockIdx.x * 32, h = blockIdx.y;
    int tid = threadIdx.x;
    int il = tid >> 3, c0 = tid & 7;

    for (int e = tid; e < 16384; e += 256) {
        int j = e >> 4, cc = e & 15;
        Vs[j * 17 + cc] = g_vals[(size_t)j * 128 + h * 16 + cc];
    }

    float acc0 = 0.f, acc1 = 0.f;
    for (int jt = 0; jt < 8; jt++) {
        __syncthreads();
        for (int e = tid; e < 1024; e += 256) {
            int r = e >> 5, q = e & 31;
            const __half* src = g_probs + ((size_t)(i0 + r) * 8 + h) * 1024 + jt * 128;
            Psu[r * 33 + q] = *(const uint2*)(src + q * 4);
        }
        __syncthreads();
        const __half2* prow = (const __half2*)(Ps + il * 132);
        const float* vbase = Vs + (jt * 128) * 17;
#pragma unroll 8
        for (int jj2 = 0; jj2 < 64; jj2++) {
            float2 pf = __half22float2(prow[jj2]);
            const float* v0 = vbase + (2 * jj2) * 17;
            acc0 += pf.x * v0[c0]      + pf.y * v0[17 + c0];
            acc1 += pf.x * v0[c0 + 8]  + pf.y * v0[17 + c0 + 8];
        }
    }
    int o = (i0 + il) * 128 + h * 16 + c0;
    out[o]     = fmaxf(acc0 + g_skip[o], 0.f);
    out[o + 8] = fmaxf(acc1 + g_skip[o + 8], 0.f);
}

// ---------------- launch ----------------
extern "C" void kernel_launch(void* const* d_in, const int* in_sizes, int n_in,
                              void* d_out, int out_size) {
    const float* node   = (const float*)d_in[0];
    const float* edge   = (const float*)d_in[1];
    const float* graph  = (const float*)d_in[2];
    const int*   adj    = (const int*)  d_in[3];
    const float* hidden = (const float*)d_in[4];
    const float* Wm     = (const float*)d_in[5];
    const float* bm     = (const float*)d_in[6];
    const float* Wskip  = (const float*)d_in[7];
    const float* bskip  = (const float*)d_in[8];
    const float* W1     = (const float*)d_in[9];
    const float* b1     = (const float*)d_in[10];
    const float* W2     = (const float*)d_in[11];
    const float* b2     = (const float*)d_in[12];
    const float* We     = (const float*)d_in[13];
    const float* be     = (const float*)d_in[14];
    const float* Wg     = (const float*)d_in[15];
    const float* bg     = (const float*)d_in[16];
    const float* Aw     = (const float*)d_in[17];
    const float* Abv    = (const float*)d_in[18];
    float* out = (float*)d_out;

    k0_gterm<<<1, 128>>>(graph, Wg, bg, be);
    k1_fused<<<dim3(64, 4), 256>>>(node, hidden, Wm, bm, Wskip, bskip, W1, b1, W2, b2);

    const int smem2 = (2 * 5120 + 128 * 136) * sizeof(__half);   // 55,296 B
    cudaFuncSetAttribute(k2_logits, cudaFuncAttributeMaxDynamicSharedMemorySize, smem2);
    k2_logits<<<296, 256, smem2>>>(edge, We, Aw, Abv, adj);

    k3a_softmax<<<1024, 256>>>();

    const int smem3 = 1024 * 17 * sizeof(float) + 32 * 132 * sizeof(__half);    // 78,080 B
    cudaFuncSetAttribute(k3b_av, cudaFuncAttributeMaxDynamicSharedMemorySize, smem3);
    k3b_av<<<dim3(32, 8), 256, smem3>>>(out);
}

// round 14
// speedup vs baseline: 1.9971x; 1.0965x over previous
#include <cuda_runtime.h>
#include <cuda_fp16.h>
#include <cstdint>

#define NN 1024

// ---------------- scratch (device globals; no allocs) ----------------
__device__ float g_pre1[NN * 128];        // [j][m]
__device__ float g_pre2g[NN * 128];
__device__ float g_vals[NN * 128];        // [j][c]
__device__ float g_skip[NN * 128];
__device__ float g_gterm[128];
__device__ float g_logits[(size_t)8 * NN * NN];   // [i][h][j]
__device__ __half g_probs[(size_t)8 * NN * NN];   // normalized softmax probs, fp16

// ---------------- helpers ----------------
__device__ __forceinline__ unsigned h2u(__half2 h) { return *(unsigned*)&h; }

// ---------------- K0 ----------------
__global__ void k0_gterm(const float* __restrict__ gf, const float* __restrict__ Wg,
                         const float* __restrict__ bg, const float* __restrict__ be) {
    int m = threadIdx.x;
    float a = bg[m] + be[m];
#pragma unroll 8
    for (int k = 0; k < 128; k++) a += gf[k] * Wg[k * 128 + m];
    g_gterm[m] = a;
}

// ---------------- K1 (fused 4 projections) ----------------
__global__ __launch_bounds__(256) void k1_fused(const float* __restrict__ node,
                                                const float* __restrict__ hid,
                                                const float* __restrict__ Wm, const float* __restrict__ bm,
                                                const float* __restrict__ Wsk, const float* __restrict__ bsk,
                                                const float* __restrict__ W1, const float* __restrict__ b1,
                                                const float* __restrict__ W2, const float* __restrict__ b2) {
    __shared__ float Ws[32 * 132];
    __shared__ float zs[16 * 33];
    int by = blockIdx.y;
    const float* W    = by == 0 ? Wm : by == 1 ? Wsk : by == 2 ? W1 : W2;
    const float* bias = by == 0 ? bm : by == 1 ? bsk : by == 2 ? b1 : b2;

    int tid = threadIdx.x, lane = tid & 31, warp = tid >> 5;
    int j0 = blockIdx.x * 16;
    float acc[2][4] = {};
    for (int kc = 0; kc < 8; kc++) {
        int kb = kc * 32;
        __syncthreads();
        for (int e = tid; e < 4096; e += 256) {
            int kl = e >> 7, m = e & 127;
            Ws[kl * 132 + m] = W[(kb + kl) * 128 + m];
        }
        for (int e = tid; e < 512; e += 256) {
            int jl = e >> 5, kl = e & 31;
            int k = kb + kl;
            zs[jl * 33 + kl] = (k < 128) ? node[(j0 + jl) * 128 + k]
                                         : hid[(j0 + jl) * 128 + k - 128];
        }
        __syncthreads();
#pragma unroll 8
        for (int kl = 0; kl < 32; kl++) {
            float4 wv = *(const float4*)&Ws[kl * 132 + lane * 4];
#pragma unroll
            for (int r = 0; r < 2; r++) {
                float zv = zs[(warp * 2 + r) * 33 + kl];
                acc[r][0] += zv * wv.x; acc[r][1] += zv * wv.y;
                acc[r][2] += zv * wv.z; acc[r][3] += zv * wv.w;
            }
        }
    }
    float4 bv = *(const float4*)&bias[lane * 4];
    float4 gv = make_float4(0.f, 0.f, 0.f, 0.f);
    if (by == 3) gv = *(const float4*)&g_gterm[lane * 4];
    float* out = by == 0 ? g_vals : by == 1 ? g_skip : by == 2 ? g_pre1 : g_pre2g;
#pragma unroll
    for (int r = 0; r < 2; r++) {
        int j = j0 + warp * 2 + r;
        float4 o;
        o.x = acc[r][0] + bv.x + gv.x;
        o.y = acc[r][1] + bv.y + gv.y;
        o.z = acc[r][2] + bv.z + gv.z;
        o.w = acc[r][3] + bv.w + gv.w;
        *(float4*)&out[(size_t)j * 128 + lane * 4] = o;
    }
}

// ---------------- K2: persistent fp16 m16n8k16 with FP16 ACCUMULATORS ----------------
// Grid 296 (2/SM). Item = (i, jt): 128x128x128 tile + fused epilogue. 8192 items.
// 8 warps = 2(wm) x 4(wn), warp tile 64m x 32n. A ring: 3 buffers of 128x32 fp16 (stride 40).
// B = We^T fp16 (stride 136), staged once. One __syncthreads per chunk.
__global__ __launch_bounds__(256, 2) void k2_logits(const float* __restrict__ edge,
                                                    const float* __restrict__ We,
                                                    const float* __restrict__ Aw,
                                                    const float* __restrict__ Abv,
                                                    const int* __restrict__ adj) {
    extern __shared__ __half sh[];
    __half* Abuf = sh;                            // 3 x 5120 halfs
    __half* Bsh = sh + 15360;                     // 128*136 halfs
    __shared__ float sAw[128], sAb[8];

    int tid = threadIdx.x, lane = tid & 31, warp = tid >> 5;
    int wm = warp >> 2, wn = warp & 3;
    int ro = lane >> 2, kq = lane & 3;

    int p = blockIdx.x;                            // 0..295
    int npi = 27 + (p < 200);
    int start = p * 27 + (p < 200 ? p : 200);
    int nchunks = npi * 4;

    // stage B = We^T fp16 once
    for (int e = tid; e < 16384; e += 256) {
        int k = e >> 7, m = e & 127;
        Bsh[m * 136 + k] = __float2half_rn(We[k * 128 + m]);
    }
    if (tid < 128) sAw[tid] = Aw[tid];
    if (tid < 8)   sAb[tid] = Abv[tid];

    auto chunk_src = [&](int cidx) -> const float* {
        int item = start + (cidx >> 2);
        int i = item >> 3, jt = item & 7, kc = cidx & 3;
        return edge + (size_t)i * 131072 + (size_t)(jt * 128) * 128 + kc * 32;
    };
    auto ldg_chunk = [&](int cidx, float4* r) {
        const float* src = chunk_src(cidx);
#pragma unroll
        for (int it = 0; it < 4; it++) {
            int idx = it * 256 + tid;
            r[it] = __ldg((const float4*)(src + (idx >> 3) * 128 + (idx & 7) * 4));
        }
    };
    auto sts_chunk = [&](const float4* r, __half* dst) {
#pragma unroll
        for (int it = 0; it < 4; it++) {
            int idx = it * 256 + tid;
            int row = idx >> 3, q = idx & 7;
            __half2 h0 = __floats2half2_rn(r[it].x, r[it].y);
            __half2 h1 = __floats2half2_rn(r[it].z, r[it].w);
            *(uint2*)(dst + row * 40 + q * 4) = make_uint2(h2u(h0), h2u(h1));
        }
    };

    // prologue: chunk 0 staged, chunk 1 in registers
    float4 rg[4];
    ldg_chunk(0, rg);
    sts_chunk(rg, Abuf);
    ldg_chunk(1, rg);
    __syncthreads();

    unsigned acc[4][4][2];        // half2 accumulators: [mi][ni][rr]
#pragma unroll
    for (int mi = 0; mi < 4; mi++)
#pragma unroll
        for (int ni = 0; ni < 4; ni++) { acc[mi][ni][0] = 0u; acc[mi][ni][1] = 0u; }

    for (int cidx = 0; cidx < nchunks; cidx++) {
        const __half* Ab = Abuf + (cidx % 3) * 5120;
        int kc = cidx & 3;

        // MMA phase (fp16 D/C)
#pragma unroll
        for (int ks = 0; ks < 2; ks++) {
            int kf = ks * 16 + 2 * kq;
            int kg = kc * 32 + kf;
            unsigned b[4][2];
#pragma unroll
            for (int ni = 0; ni < 4; ni++) {
                const __half* bp = Bsh + (wn * 32 + ni * 8 + ro) * 136 + kg;
                b[ni][0] = *(const unsigned*)bp;
                b[ni][1] = *(const unsigned*)(bp + 8);
            }
#pragma unroll
            for (int mi = 0; mi < 4; mi++) {
                int r0 = (wm * 64 + mi * 16 + ro) * 40 + kf;
                unsigned a0 = *(const unsigned*)(Ab + r0);
                unsigned a1 = *(const unsigned*)(Ab + r0 + 320);
                unsigned a2 = *(const unsigned*)(Ab + r0 + 8);
                unsigned a3 = *(const unsigned*)(Ab + r0 + 328);
#pragma unroll
                for (int ni = 0; ni < 4; ni++)
                    asm volatile(
                        "mma.sync.aligned.m16n8k16.row.col.f16.f16.f16.f16 "
                        "{%0,%1}, {%2,%3,%4,%5}, {%6,%7}, {%0,%1};"
                        : "+r"(acc[mi][ni][0]), "+r"(acc[mi][ni][1])
                        : "r"(a0), "r"(a1), "r"(a2), "r"(a3),
                          "r"(b[ni][0]), "r"(b[ni][1]));
            }
        }

        if (kc == 3) {
            // epilogue for finished item
            int item = start + (cidx >> 2);
            int i = item >> 3, j0 = (item & 7) * 128;

            float p2x[4], p2y[4];
#pragma unroll
            for (int ni = 0; ni < 4; ni++) {
                int cb = wn * 32 + ni * 8 + kq * 2;
                float2 pv = __ldg((const float2*)&g_pre2g[i * 128 + cb]);
                p2x[ni] = pv.x; p2y[ni] = pv.y;
            }
            float hsum[4][2][2];
#pragma unroll
            for (int mi = 0; mi < 4; mi++)
#pragma unroll
                for (int rr = 0; rr < 2; rr++) {
                    hsum[mi][rr][0] = 0.f; hsum[mi][rr][1] = 0.f;
                }
#pragma unroll
            for (int mi = 0; mi < 4; mi++) {
#pragma unroll
                for (int rr = 0; rr < 2; rr++) {
                    int jrow = j0 + wm * 64 + mi * 16 + ro + rr * 8;
                    const float* p1 = g_pre1 + (size_t)jrow * 128;
#pragma unroll
                    for (int ni = 0; ni < 4; ni++) {
                        int cb = wn * 32 + ni * 8 + kq * 2;
                        float2 pv = __ldg((const float2*)&p1[cb]);
                        float2 cf = __half22float2(*(__half2*)&acc[mi][ni][rr]);
                        float x0 = cf.x + pv.x + p2x[ni];
                        float x1 = cf.y + pv.y + p2y[ni];
                        x0 = fmaxf(x0, 0.01f * x0);
                        x1 = fmaxf(x1, 0.01f * x1);
                        hsum[mi][rr][ni >> 1] += sAw[cb] * x0 + sAw[cb + 1] * x1;
                    }
                }
            }
#pragma unroll
            for (int off = 1; off <= 2; off <<= 1)
#pragma unroll
                for (int mi = 0; mi < 4; mi++)
#pragma unroll
                    for (int rr = 0; rr < 2; rr++) {
                        hsum[mi][rr][0] += __shfl_xor_sync(0xffffffffu, hsum[mi][rr][0], off);
                        hsum[mi][rr][1] += __shfl_xor_sync(0xffffffffu, hsum[mi][rr][1], off);
                    }
            int q = lane & 3;
            if (q < 2) {
                int h = wn * 2 + q;
                float ab = sAb[h];
#pragma unroll
                for (int mi = 0; mi < 4; mi++)
#pragma unroll
                    for (int rr = 0; rr < 2; rr++) {
                        int j = j0 + wm * 64 + mi * 16 + ro + rr * 8;
                        float lg = hsum[mi][rr][q] + ab
                                 + (__ldg(&adj[i * 1024 + j]) ? 0.f : -1e9f);
                        g_logits[((size_t)i * 8 + h) * 1024 + j] = lg;
                    }
            }
#pragma unroll
            for (int mi = 0; mi < 4; mi++)
#pragma unroll
                for (int ni = 0; ni < 4; ni++) { acc[mi][ni][0] = 0u; acc[mi][ni][1] = 0u; }
        }

        // stage chunk cidx+1 (data already in regs) into ring slot, then LDG cidx+2
        if (cidx + 1 < nchunks) sts_chunk(rg, Abuf + ((cidx + 1) % 3) * 5120);
        if (cidx + 2 < nchunks) ldg_chunk(cidx + 2, rg);
        __syncthreads();
    }
}

// ---------------- K3a: softmax -> normalized fp16 probs ----------------
__global__ __launch_bounds__(256) void k3a_softmax() {
    int i = blockIdx.x;
    int tid = threadIdx.x, lane = tid & 31, h = tid >> 5;
    const float* lg = g_logits + ((size_t)(i * 8 + h)) * 1024;

    float4 v[8];
#pragma unroll
    for (int t = 0; t < 8; t++) v[t] = ((const float4*)lg)[t * 32 + lane];
    float mx = -3.402823e38f;
#pragma unroll
    for (int t = 0; t < 8; t++)
        mx = fmaxf(mx, fmaxf(fmaxf(v[t].x, v[t].y), fmaxf(v[t].z, v[t].w)));
#pragma unroll
    for (int off = 16; off >= 1; off >>= 1)
        mx = fmaxf(mx, __shfl_xor_sync(0xffffffffu, mx, off));
    float ssum = 0.f;
#pragma unroll
    for (int t = 0; t < 8; t++) {
        v[t].x = __expf(v[t].x - mx); v[t].y = __expf(v[t].y - mx);
        v[t].z = __expf(v[t].z - mx); v[t].w = __expf(v[t].w - mx);
        ssum += v[t].x + v[t].y + v[t].z + v[t].w;
    }
#pragma unroll
    for (int off = 16; off >= 1; off >>= 1)
        ssum += __shfl_xor_sync(0xffffffffu, ssum, off);
    float inv = 1.f / ssum;

    __half* pr = g_probs + ((size_t)(i * 8 + h)) * 1024;
#pragma unroll
    for (int t = 0; t < 8; t++) {
        __half2 ha = __floats2half2_rn(v[t].x * inv, v[t].y * inv);
        __half2 hb = __floats2half2_rn(v[t].z * inv, v[t].w * inv);
        *(uint2*)&pr[(t * 32 + lane) * 4] = make_uint2(h2u(ha), h2u(hb));
    }
}

// ---------------- K3b: AV + skip + relu ----------------
__global__ __launch_bounds__(256) void k3b_av(float* __restrict__ out) {
    extern __shared__ float s3[];
    float* Vs = s3;                                  // 1024*17 floats
    __half* Ps = (__half*)(s3 + 1024 * 17);          // 32*132 halfs
    uint2* Psu = (uint2*)Ps;

    int i0 = blockIdx.x * 32, h = blockIdx.y;
    int tid = threadIdx.x;
    int il = tid >> 3, c0 = tid & 7;

    for (int e = tid; e < 16384; e += 256) {
        int j = e >> 4, cc = e & 15;
        Vs[j * 17 + cc] = g_vals[(size_t)j * 128 + h * 16 + cc];
    }

    float acc0 = 0.f, acc1 = 0.f;
    for (int jt = 0; jt < 8; jt++) {
        __syncthreads();
        for (int e = tid; e < 1024; e += 256) {
            int r = e >> 5, q = e & 31;
            const __half* src = g_probs + ((size_t)(i0 + r) * 8 + h) * 1024 + jt * 128;
            Psu[r * 33 + q] = *(const uint2*)(src + q * 4);
        }
        __syncthreads();
        const __half2* prow = (const __half2*)(Ps + il * 132);
        const float* vbase = Vs + (jt * 128) * 17;
#pragma unroll 8
        for (int jj2 = 0; jj2 < 64; jj2++) {
            float2 pf = __half22float2(prow[jj2]);
            const float* v0 = vbase + (2 * jj2) * 17;
            acc0 += pf.x * v0[c0]      + pf.y * v0[17 + c0];
            acc1 += pf.x * v0[c0 + 8]  + pf.y * v0[17 + c0 + 8];
        }
    }
    int o = (i0 + il) * 128 + h * 16 + c0;
    out[o]     = fmaxf(acc0 + g_skip[o], 0.f);
    out[o + 8] = fmaxf(acc1 + g_skip[o + 8], 0.f);
}

// ---------------- launch ----------------
extern "C" void kernel_launch(void* const* d_in, const int* in_sizes, int n_in,
                              void* d_out, int out_size) {
    const float* node   = (const float*)d_in[0];
    const float* edge   = (const float*)d_in[1];
    const float* graph  = (const float*)d_in[2];
    const int*   adj    = (const int*)  d_in[3];
    const float* hidden = (const float*)d_in[4];
    const float* Wm     = (const float*)d_in[5];
    const float* bm     = (const float*)d_in[6];
    const float* Wskip  = (const float*)d_in[7];
    const float* bskip  = (const float*)d_in[8];
    const float* W1     = (const float*)d_in[9];
    const float* b1     = (const float*)d_in[10];
    const float* W2     = (const float*)d_in[11];
    const float* b2     = (const float*)d_in[12];
    const float* We     = (const float*)d_in[13];
    const float* be     = (const float*)d_in[14];
    const float* Wg     = (const float*)d_in[15];
    const float* bg     = (const float*)d_in[16];
    const float* Aw     = (const float*)d_in[17];
    const float* Abv    = (const float*)d_in[18];
    float* out = (float*)d_out;

    k0_gterm<<<1, 128>>>(graph, Wg, bg, be);
    k1_fused<<<dim3(64, 4), 256>>>(node, hidden, Wm, bm, Wskip, bskip, W1, b1, W2, b2);

    const int smem2 = (3 * 5120 + 128 * 136) * sizeof(__half);   // 65,536 B
    cudaFuncSetAttribute(k2_logits, cudaFuncAttributeMaxDynamicSharedMemorySize, smem2);
    k2_logits<<<296, 256, smem2>>>(edge, We, Aw, Abv, adj);

    k3a_softmax<<<1024, 256>>>();

    const int smem3 = 1024 * 17 * sizeof(float) + 32 * 132 * sizeof(__half);    // 78,080 B
    cudaFuncSetAttribute(k3b_av, cudaFuncAttributeMaxDynamicSharedMemorySize, smem3);
    k3b_av<<<dim3(32, 8), 256, smem3>>>(out);
}